// round 5
// baseline (speedup 1.0000x reference)
#include <cuda_runtime.h>

#define BATCH   8
#define TSTEPS  12
#define CIN_X   5
#define HID     16
#define CIN_ALL (CIN_X + HID)      /* 21 */
#define IMG     256
#define WPERC   (CIN_ALL * 9)      /* 189 taps per hid per gate */
#define TILE    16
#define NTHREADS 512

/* smem layout:
   floats [0, 12096):   weights reordered [hid16][ci21][tap9][gate4] (48384 B)
   floats [12096, ..):  pixel tile (plain): [21 ci][18 r][22 stride]  (33264 B)
   stride 22: 22r mod 32 distinct for r=0..15 -> conflict-free LDS.64
*/
#define W_FLOATS  (64 * WPERC)              /* 12096 */
#define TSTRIDE   22
#define T_PER_CI  (18 * TSTRIDE)            /* 396 */
#define SMEM_BYTES ((W_FLOATS + CIN_ALL * T_PER_CI) * 4)   /* 81648 */

__device__ float g_h[2][BATCH * HID * IMG * IMG];
__device__ float g_c[BATCH * HID * IMG * IMG];
__device__ float4 g_wre[16 * WPERC];        /* reordered weights [hid][tap][gate4] */

typedef unsigned long long u64;

__device__ __forceinline__ u64 pk2(float lo, float hi) {
    u64 r; asm("mov.b64 %0, {%1, %2};" : "=l"(r) : "f"(lo), "f"(hi)); return r;
}
__device__ __forceinline__ void upk2(u64 v, float &lo, float &hi) {
    asm("mov.b64 {%0, %1}, %2;" : "=f"(lo), "=f"(hi) : "l"(v));
}
#define FFMA2(acc, a, b) asm("fma.rn.f32x2 %0, %1, %2, %0;" : "+l"(acc) : "l"(a), "l"(b))

__device__ __forceinline__ float sig_(float x)  { return 1.0f / (1.0f + __expf(-x)); }
__device__ __forceinline__ float tanh_(float x) { return 2.0f / (1.0f + __expf(-2.0f * x)) - 1.0f; }

// One-shot weight reorder: g_wre[hid][tap] = (Wi, Wf, Wo, Wg) for that tap.
__global__ void reorder_weights_kernel(const float* __restrict__ Wc)
{
    int i = blockIdx.x * blockDim.x + threadIdx.x;
    if (i >= 16 * WPERC) return;
    int hid = i / WPERC;
    int tap = i - hid * WPERC;
    float4 v;
    v.x = Wc[(hid     ) * WPERC + tap];
    v.y = Wc[(hid + 16) * WPERC + tap];
    v.z = Wc[(hid + 32) * WPERC + tap];
    v.w = Wc[(hid + 48) * WPERC + tap];
    g_wre[i] = v;
}

// Fused ConvLSTM step. Block = 16x16 tile x 16 hid (warp==hid), 2 CTAs/SM.
// FFMA2 pairs gates: acc_if[p]=(i,f), acc_og[p]=(o,g), 8 pixels/thread.
// Pixel tile un-duplicated; (v,v) operand built by 1 mov per pixel (ALU idle).
__global__ void __launch_bounds__(NTHREADS, 2)
lstm_step_kernel(const float* __restrict__ xall, const float* __restrict__ bc, int t)
{
    extern __shared__ float smem[];
    float* s_w = smem;                      // [16][189] float4 view
    float* s_t = smem + W_FLOATS;           // [21][18][22] plain floats

    const int tid = threadIdx.x;
    const int b  = blockIdx.z;
    const int y0 = blockIdx.y * TILE;
    const int x0 = blockIdx.x * TILE;
    const int first = (t == 0);
    const int ncin  = first ? CIN_X : CIN_ALL;

    const float* h_prev = g_h[t & 1];
    float*       h_next = g_h[(t + 1) & 1];

    // Weights -> smem (coalesced float4 copy of the pre-reordered array)
    #pragma unroll 1
    for (int i = tid; i < 16 * WPERC; i += NTHREADS)
        ((float4*)s_w)[i] = g_wre[i];

    // Input tile (+halo) -> smem, plain floats.
    {
        const int ntile = ncin * 18 * 18;
        #pragma unroll 1
        for (int i = tid; i < ntile; i += NTHREADS) {
            int ci  = i / (18 * 18);
            int rem = i - ci * (18 * 18);
            int r   = rem / 18;
            int mi  = rem - r * 18;                 // 0..17 == col -1..16
            int gy = y0 + r - 1, gx = x0 + mi - 1;
            float v = 0.0f;
            if ((unsigned)gy < IMG && (unsigned)gx < IMG) {
                if (ci < CIN_X)
                    v = xall[(((b * TSTEPS + t) * CIN_X + ci) << 16) + (gy << 8) + gx];
                else
                    v = h_prev[((b * HID + (ci - CIN_X)) << 16) + (gy << 8) + gx];
            }
            s_t[ci * T_PER_CI + r * TSTRIDE + mi] = v;
        }
    }
    __syncthreads();

    const int hid  = tid >> 5;       // warp-uniform
    const int lane = tid & 31;
    const int row  = lane & 15;
    const int xg   = lane >> 4;      // pixels xg*8 .. xg*8+7

    u64 acc_if[8], acc_og[8];
    #pragma unroll
    for (int p = 0; p < 8; ++p) { acc_if[p] = 0ULL; acc_og[p] = 0ULL; }

    #pragma unroll 1
    for (int ci = 0; ci < ncin; ++ci) {
        const float* tbase = s_t + ci * T_PER_CI + row * TSTRIDE + xg * 8;
        const ulonglong2* wci = (const ulonglong2*)s_w + hid * WPERC + ci * 9;
        #pragma unroll
        for (int ky = 0; ky < 3; ++ky) {
            const float* tr = tbase + ky * TSTRIDE;   // even float offset -> 8B aligned
            float2 a0 = *(const float2*)(tr + 0);
            float2 a1 = *(const float2*)(tr + 2);
            float2 a2 = *(const float2*)(tr + 4);
            float2 a3 = *(const float2*)(tr + 6);
            float2 a4 = *(const float2*)(tr + 8);
            // weight packs: .x = (wi,wf), .y = (wo,wg)
            ulonglong2 w0 = wci[ky * 3 + 0];
            ulonglong2 w1 = wci[ky * 3 + 1];
            ulonglong2 w2 = wci[ky * 3 + 2];
            float rr[10] = { a0.x, a0.y, a1.x, a1.y, a2.x,
                             a2.y, a3.x, a3.y, a4.x, a4.y };
            #pragma unroll
            for (int k = 0; k < 10; ++k) {
                u64 pv = pk2(rr[k], rr[k]);          // 1 ALU mov, consumed immediately
                if (k <= 7)           { FFMA2(acc_if[k],     pv, w0.x); FFMA2(acc_og[k],     pv, w0.y); }
                if (k >= 1 && k <= 8) { FFMA2(acc_if[k - 1], pv, w1.x); FFMA2(acc_og[k - 1], pv, w1.y); }
                if (k >= 2)           { FFMA2(acc_if[k - 2], pv, w2.x); FFMA2(acc_og[k - 2], pv, w2.y); }
            }
        }
    }

    // Epilogue: gates + state update for 8 pixels.
    const float bi  = bc[hid];
    const float bfv = bc[hid + 16];
    const float bo  = bc[hid + 32];
    const float bg  = bc[hid + 48];
    const int base = ((b * HID + hid) << 16) + ((y0 + row) << 8) + x0 + xg * 8;

    float cold[8];
    if (!first) {
        float4 ca = *(const float4*)(g_c + base);
        float4 cb = *(const float4*)(g_c + base + 4);
        cold[0] = ca.x; cold[1] = ca.y; cold[2] = ca.z; cold[3] = ca.w;
        cold[4] = cb.x; cold[5] = cb.y; cold[6] = cb.z; cold[7] = cb.w;
    } else {
        #pragma unroll
        for (int p = 0; p < 8; ++p) cold[p] = 0.0f;
    }

    float cn[8], hn[8];
    #pragma unroll
    for (int p = 0; p < 8; ++p) {
        float iv, fv, ov, gv;
        upk2(acc_if[p], iv, fv);
        upk2(acc_og[p], ov, gv);
        float i = sig_(iv + bi),  f = sig_(fv + bfv);
        float o = sig_(ov + bo),  g = tanh_(gv + bg);
        float c = f * cold[p] + i * g;
        cn[p] = c; hn[p] = o * tanh_(c);
    }
    *(float4*)(g_c + base)        = make_float4(cn[0], cn[1], cn[2], cn[3]);
    *(float4*)(g_c + base + 4)    = make_float4(cn[4], cn[5], cn[6], cn[7]);
    *(float4*)(h_next + base)     = make_float4(hn[0], hn[1], hn[2], hn[3]);
    *(float4*)(h_next + base + 4) = make_float4(hn[4], hn[5], hn[6], hn[7]);
}

// Final 1x1 conv over h_last (g_h[0] after 12 steps).
__global__ void final_conv_kernel(const float* __restrict__ Wf,
                                  const float* __restrict__ bfin,
                                  float* __restrict__ out)
{
    const int total4 = BATCH * IMG * IMG / 4;
    int idx4 = blockIdx.x * blockDim.x + threadIdx.x;
    if (idx4 >= total4) return;
    const float* h = g_h[TSTEPS & 1];
    int b    = idx4 >> 14;
    int pix4 = idx4 & 16383;
    float w[HID];
    #pragma unroll
    for (int j = 0; j < HID; ++j) w[j] = Wf[j];
    float bv = bfin[0];
    float4 a; a.x = bv; a.y = bv; a.z = bv; a.w = bv;
    #pragma unroll
    for (int j = 0; j < HID; ++j) {
        float4 v = *(const float4*)(h + ((b * HID + j) << 16) + pix4 * 4);
        a.x += w[j] * v.x; a.y += w[j] * v.y;
        a.z += w[j] * v.z; a.w += w[j] * v.w;
    }
    ((float4*)out)[idx4] = a;
}

extern "C" void kernel_launch(void* const* d_in, const int* in_sizes, int n_in,
                              void* d_out, int out_size)
{
    const float* x  = (const float*)d_in[0];
    const float* Wc = (const float*)d_in[1];
    const float* bc = (const float*)d_in[2];
    const float* Wf = (const float*)d_in[3];
    const float* bf = (const float*)d_in[4];
    float* out = (float*)d_out;

    cudaFuncSetAttribute(lstm_step_kernel,
                         cudaFuncAttributeMaxDynamicSharedMemorySize, SMEM_BYTES);

    reorder_weights_kernel<<<(16 * WPERC + 255) / 256, 256>>>(Wc);

    dim3 grid(IMG / TILE, IMG / TILE, BATCH);
    for (int t = 0; t < TSTEPS; ++t)
        lstm_step_kernel<<<grid, NTHREADS, SMEM_BYTES>>>(x, bc, t);

    const int total4 = BATCH * IMG * IMG / 4;
    final_conv_kernel<<<(total4 + 255) / 256, 256>>>(Wf, bf, out);
}

// round 7
// speedup vs baseline: 1.0666x; 1.0666x over previous
#include <cuda_runtime.h>
#include <cuda_bf16.h>
#include <cstdint>

#define BATCH   8
#define TSTEPS  12
#define CIN_X   5
#define HID     16
#define IMG     256
#define NTHREADS 256

/* smem byte offsets (step kernel) */
#define SM_AH(dy)  ((dy) * 16384)                 /* A-hi: 3 x [128 rows][64 bf16] */
#define SM_AL(dy)  (49152 + (dy) * 16384)         /* A-lo */
#define SM_BH(dy)  (98304 + (dy) * 8192)          /* B-hi: 3 x [64 rows][64 bf16] */
#define SM_BL(dy)  (122880 + (dy) * 8192)         /* B-lo */
#define SMEM_TOTAL 147456
#define STAGE_STRIDE 66                           /* f32 stage stride, reuses A region */

__device__ float g_h[2][BATCH * HID * IMG * IMG];
__device__ float g_c[BATCH * HID * IMG * IMG];
__device__ uint4 g_Bh[3 * 512];                   /* swizzled smem images of B hi/lo */
__device__ uint4 g_Bl[3 * 512];

__device__ __forceinline__ uint32_t smem_u32(const void* p) {
    uint32_t a;
    asm("{ .reg .u64 t; cvta.to.shared.u64 t, %1; cvt.u32.u64 %0, t; }" : "=r"(a) : "l"(p));
    return a;
}
__device__ __forceinline__ void ldsm4(uint32_t* r, uint32_t addr) {
    asm volatile("ldmatrix.sync.aligned.m8n8.x4.shared.b16 {%0,%1,%2,%3}, [%4];"
                 : "=r"(r[0]), "=r"(r[1]), "=r"(r[2]), "=r"(r[3]) : "r"(addr));
}
__device__ __forceinline__ void mma16816(float* c, const uint32_t* a, uint32_t b0, uint32_t b1) {
    asm volatile("mma.sync.aligned.m16n8k16.row.col.f32.bf16.bf16.f32 "
                 "{%0,%1,%2,%3}, {%4,%5,%6,%7}, {%8,%9}, {%0,%1,%2,%3};"
                 : "+f"(c[0]), "+f"(c[1]), "+f"(c[2]), "+f"(c[3])
                 : "r"(a[0]), "r"(a[1]), "r"(a[2]), "r"(a[3]), "r"(b0), "r"(b1));
}
__device__ __forceinline__ float sig_(float x)  { return 1.0f / (1.0f + __expf(-x)); }
__device__ __forceinline__ float tanh_(float x) { return 2.0f / (1.0f + __expf(-2.0f * x)) - 1.0f; }

/* split 8 fp32 -> hi/lo bf16x2 packs (4 + 4 regs) */
__device__ __forceinline__ void split8(const float* v, uint32_t* hp, uint32_t* lp) {
    #pragma unroll
    for (int jj = 0; jj < 4; ++jj) {
        __nv_bfloat16 h0 = __float2bfloat16(v[2 * jj]);
        __nv_bfloat16 h1 = __float2bfloat16(v[2 * jj + 1]);
        __nv_bfloat16 l0 = __float2bfloat16(v[2 * jj]     - __bfloat162float(h0));
        __nv_bfloat16 l1 = __float2bfloat16(v[2 * jj + 1] - __bfloat162float(h1));
        hp[jj] = (uint32_t)__bfloat16_as_ushort(h0) | ((uint32_t)__bfloat16_as_ushort(h1) << 16);
        lp[jj] = (uint32_t)__bfloat16_as_ushort(l0) | ((uint32_t)__bfloat16_as_ushort(l1) << 16);
    }
}

/* Precompute B hi/lo swizzled smem images. grid 1, 192 threads: (dy, n). */
__global__ void build_B_kernel(const float* __restrict__ Wc)
{
    const int tid = threadIdx.x;
    if (tid >= 192) return;
    const int dy = tid >> 6;
    const int n  = tid & 63;
    #pragma unroll
    for (int i = 0; i < 8; ++i) {
        float v[8];
        #pragma unroll
        for (int j = 0; j < 8; ++j) {
            const int k  = i * 8 + j;
            const int ch = k / 3;
            const int dx = k - ch * 3;
            v[j] = (ch < 21) ? Wc[n * 189 + ch * 9 + dy * 3 + dx] : 0.0f;
        }
        uint32_t hp[4], lp[4];
        split8(v, hp, lp);
        uint32_t off = (uint32_t)(n * 128 + i * 16);
        off ^= (uint32_t)((n & 7) << 4);                /* SW128 swizzle */
        const int idx = (dy * 8192 + (int)off) >> 4;
        g_Bh[idx] = make_uint4(hp[0], hp[1], hp[2], hp[3]);
        g_Bl[idx] = make_uint4(lp[0], lp[1], lp[2], lp[3]);
    }
}

/* Fused ConvLSTM step via bf16 mma.sync implicit GEMM.
   CTA: (b, y, x0) strip of 128 px. D[128 px][64 ch] = sum over 3 dy, 3 comp passes.
   8 warps = 4 (m) x 2 (n), warp tile 32x32, mma m16n8k16. */
__global__ void __launch_bounds__(NTHREADS, 1)
lstm_step_kernel(const float* __restrict__ xall, const float* __restrict__ bc, int t)
{
    extern __shared__ char smem[];
    const uint32_t sb = smem_u32(smem);
    float* s_stage = (float*)smem;                  /* epilogue stage over A region */

    const int tid  = threadIdx.x;
    const int wid  = tid >> 5;
    const int lane = tid & 31;
    const int b  = blockIdx.z;
    const int y  = blockIdx.y;
    const int x0 = blockIdx.x << 7;
    const int first = (t == 0);

    const float* h_prev = g_h[t & 1];
    float*       h_next = g_h[(t + 1) & 1];

    /* ---- copy precomputed B images (48 KB) ---- */
    {
        uint4* dstH = (uint4*)(smem + SM_BH(0));
        uint4* dstL = (uint4*)(smem + SM_BL(0));
        #pragma unroll 1
        for (int i = tid; i < 1536; i += NTHREADS) { dstH[i] = g_Bh[i]; dstL[i] = g_Bl[i]; }
    }
    /* ---- build A hi/lo (im2col, swizzled): items (dy, m) ---- */
    #pragma unroll 1
    for (int it = tid; it < 384; it += NTHREADS) {
        const int dy = it >> 7;
        const int m  = it & 127;
        const int gy = y - 1 + dy;
        const bool rowok = ((unsigned)gy < IMG);
        const float* xrow = xall + ((((b * TSTEPS + t) * CIN_X) << 16) + (gy << 8));
        const float* hrow = h_prev + (((b * HID) << 16) + (gy << 8));
        const int xb = x0 + m - 1;
        #pragma unroll
        for (int i = 0; i < 8; ++i) {
            float v[8];
            #pragma unroll
            for (int j = 0; j < 8; ++j) {
                const int k  = i * 8 + j;
                const int ch = k / 3;
                const int dx = k - ch * 3;
                float val = 0.0f;
                if (ch < 21) {
                    const int gx = xb + dx;
                    const bool hload = (ch >= CIN_X);
                    if (rowok && (unsigned)gx < IMG && !(first && hload))
                        val = hload ? hrow[((ch - CIN_X) << 16) + gx]
                                    : xrow[(ch << 16) + gx];
                }
                v[j] = val;
            }
            uint32_t hp[4], lp[4];
            split8(v, hp, lp);
            uint32_t off = (uint32_t)(m * 128 + i * 16);
            off ^= (uint32_t)((m & 7) << 4);
            *(uint4*)(smem + SM_AH(dy) + off) = make_uint4(hp[0], hp[1], hp[2], hp[3]);
            *(uint4*)(smem + SM_AL(dy) + off) = make_uint4(lp[0], lp[1], lp[2], lp[3]);
        }
    }
    __syncthreads();

    /* ---- mainloop ---- */
    const int wm = wid >> 1;            /* 0..3 -> m_base = wm*32 */
    const int wn = wid & 1;             /* 0..1 -> n_base = wn*32 */
    const int m_base = wm * 32;
    const int n_base = wn * 32;
    const int j  = lane >> 3;           /* ldmatrix matrix index 0..3 */
    const int r  = lane & 7;

    /* A lane offsets (mt = 0,1): matrix order (m0-7,k0)(m8-15,k0)(m0-7,k8)(m8-15,k8) */
    uint32_t offA[2], offB[2];
    #pragma unroll
    for (int mt = 0; mt < 2; ++mt) {
        const int row = m_base + mt * 16 + (j & 1) * 8 + r;
        const int c16 = j >> 1;
        offA[mt] = (uint32_t)(row * 128 + ((c16 << 4) ^ ((row & 7) << 4)));
    }
    /* B lane offsets (nb = 0,1): matrices (n0-7,k0)(n0-7,k8)(n8-15,k0)(n8-15,k8) */
    #pragma unroll
    for (int nb = 0; nb < 2; ++nb) {
        const int row = n_base + nb * 16 + (j >> 1) * 8 + r;
        const int c16 = j & 1;
        offB[nb] = (uint32_t)(row * 128 + ((c16 << 4) ^ ((row & 7) << 4)));
    }

    float acc[8][4];                    /* [mt*4 + nblk][reg] */
    #pragma unroll
    for (int q = 0; q < 8; ++q)
        #pragma unroll
        for (int e = 0; e < 4; ++e) acc[q][e] = 0.0f;

    #pragma unroll 1
    for (int dy = 0; dy < 3; ++dy) {
        #pragma unroll 1
        for (int pass = 0; pass < 3; ++pass) {
            const uint32_t Ab = sb + (pass == 1 ? SM_AL(dy) : SM_AH(dy));
            const uint32_t Bb = sb + (pass == 2 ? SM_BL(dy) : SM_BH(dy));
            #pragma unroll
            for (int kc = 0; kc < 4; ++kc) {
                const uint32_t kx = (uint32_t)(kc << 5);
                uint32_t a0[4], a1[4], b0[4], b1[4];
                ldsm4(a0, Ab + (offA[0] ^ kx));
                ldsm4(a1, Ab + (offA[1] ^ kx));
                ldsm4(b0, Bb + (offB[0] ^ kx));
                ldsm4(b1, Bb + (offB[1] ^ kx));
                mma16816(acc[0], a0, b0[0], b0[1]);
                mma16816(acc[1], a0, b0[2], b0[3]);
                mma16816(acc[2], a0, b1[0], b1[1]);
                mma16816(acc[3], a0, b1[2], b1[3]);
                mma16816(acc[4], a1, b0[0], b0[1]);
                mma16816(acc[5], a1, b0[2], b0[3]);
                mma16816(acc[6], a1, b1[0], b1[1]);
                mma16816(acc[7], a1, b1[2], b1[3]);
            }
        }
    }
    __syncthreads();                    /* all mma reads of A done before staging */

    /* ---- stage acc -> smem f32 [128][66] ---- */
    {
        const int g = lane >> 2;
        const int q = lane & 3;
        #pragma unroll
        for (int mt = 0; mt < 2; ++mt)
            #pragma unroll
            for (int nb = 0; nb < 4; ++nb) {
                const int m = m_base + mt * 16 + g;
                const int n = n_base + nb * 8 + 2 * q;
                float* p0 = s_stage + m * STAGE_STRIDE + n;
                p0[0] = acc[mt * 4 + nb][0];
                p0[1] = acc[mt * 4 + nb][1];
                float* p1 = p0 + 8 * STAGE_STRIDE;
                p1[0] = acc[mt * 4 + nb][2];
                p1[1] = acc[mt * 4 + nb][3];
            }
    }
    __syncthreads();

    /* ---- epilogue: gates + state update, thread = pixel ---- */
    if (tid < 128) {
        const int px  = tid;
        const float* sp = s_stage + px * STAGE_STRIDE;
        const int pix = (y << 8) + x0 + px;
        #pragma unroll
        for (int hid = 0; hid < HID; ++hid) {
            const float iv = sp[hid]      + bc[hid];
            const float fv = sp[hid + 16] + bc[hid + 16];
            const float ov = sp[hid + 32] + bc[hid + 32];
            const float gv = sp[hid + 48] + bc[hid + 48];
            const int idx = ((b * HID + hid) << 16) + pix;
            const float cold = first ? 0.0f : g_c[idx];
            const float i = sig_(iv), f = sig_(fv), o = sig_(ov), g = tanh_(gv);
            const float c = f * cold + i * g;
            g_c[idx]    = c;
            h_next[idx] = o * tanh_(c);
        }
    }
}

/* Final 1x1 conv over h_last (g_h[0] after 12 steps). */
__global__ void final_conv_kernel(const float* __restrict__ Wf,
                                  const float* __restrict__ bfin,
                                  float* __restrict__ out)
{
    const int total4 = BATCH * IMG * IMG / 4;
    int idx4 = blockIdx.x * blockDim.x + threadIdx.x;
    if (idx4 >= total4) return;
    const float* h = g_h[TSTEPS & 1];
    int b    = idx4 >> 14;
    int pix4 = idx4 & 16383;
    float w[HID];
    #pragma unroll
    for (int jj = 0; jj < HID; ++jj) w[jj] = Wf[jj];
    float bv = bfin[0];
    float4 a; a.x = bv; a.y = bv; a.z = bv; a.w = bv;
    #pragma unroll
    for (int jj = 0; jj < HID; ++jj) {
        float4 v = *(const float4*)(h + ((b * HID + jj) << 16) + pix4 * 4);
        a.x += w[jj] * v.x; a.y += w[jj] * v.y;
        a.z += w[jj] * v.z; a.w += w[jj] * v.w;
    }
    ((float4*)out)[idx4] = a;
}

extern "C" void kernel_launch(void* const* d_in, const int* in_sizes, int n_in,
                              void* d_out, int out_size)
{
    const float* x  = (const float*)d_in[0];
    const float* Wc = (const float*)d_in[1];
    const float* bc = (const float*)d_in[2];
    const float* Wf = (const float*)d_in[3];
    const float* bf = (const float*)d_in[4];
    float* out = (float*)d_out;

    cudaFuncSetAttribute(lstm_step_kernel,
                         cudaFuncAttributeMaxDynamicSharedMemorySize, SMEM_TOTAL);

    build_B_kernel<<<1, 192>>>(Wc);

    dim3 grid(IMG / 128, IMG, BATCH);   /* (2, 256, 8) */
    for (int t = 0; t < TSTEPS; ++t)
        lstm_step_kernel<<<grid, NTHREADS, SMEM_TOTAL>>>(x, bc, t);

    const int total4 = BATCH * IMG * IMG / 4;
    final_conv_kernel<<<(total4 + 255) / 256, 256>>>(Wf, bf, out);
}

// round 9
// speedup vs baseline: 1.7870x; 1.6754x over previous
#include <cuda_runtime.h>
#include <cuda_bf16.h>
#include <cstdint>

#define BATCH   8
#define TSTEPS  12
#define CIN_X   5
#define HID     16
#define IMG     256
#define NTHREADS 512

/* smem byte offsets:
   A-hi: [512 rows][64 bf16] = 4 input-row strips (y0-1 .. y0+2), 65536 B
   A-lo: same, at +65536
   B-hi: 3 dy x 8192 B at 131072..155648
   B-lo: 3 dy x 8192 B at 155648..180224                                 */
#define SM_AH      0
#define SM_AL      65536
#define SM_BH(dy)  (131072 + (dy) * 8192)
#define SM_BL(dy)  (155648 + (dy) * 8192)
#define SMEM_TOTAL 180224
#define STAGE_STRIDE 66                 /* f32 epilogue stage over A region */

__device__ float g_h[2][BATCH * HID * IMG * IMG];
__device__ float g_c[BATCH * HID * IMG * IMG];
__device__ uint4 g_Bh[3 * 512];
__device__ uint4 g_Bl[3 * 512];

__device__ __forceinline__ uint32_t smem_u32(const void* p) {
    uint32_t a;
    asm("{ .reg .u64 t; cvta.to.shared.u64 t, %1; cvt.u32.u64 %0, t; }" : "=r"(a) : "l"(p));
    return a;
}
__device__ __forceinline__ void ldsm4(uint32_t* r, uint32_t addr) {
    asm volatile("ldmatrix.sync.aligned.m8n8.x4.shared.b16 {%0,%1,%2,%3}, [%4];"
                 : "=r"(r[0]), "=r"(r[1]), "=r"(r[2]), "=r"(r[3]) : "r"(addr));
}
__device__ __forceinline__ void mma16816(float* c, const uint32_t* a, uint32_t b0, uint32_t b1) {
    asm volatile("mma.sync.aligned.m16n8k16.row.col.f32.bf16.bf16.f32 "
                 "{%0,%1,%2,%3}, {%4,%5,%6,%7}, {%8,%9}, {%0,%1,%2,%3};"
                 : "+f"(c[0]), "+f"(c[1]), "+f"(c[2]), "+f"(c[3])
                 : "r"(a[0]), "r"(a[1]), "r"(a[2]), "r"(a[3]), "r"(b0), "r"(b1));
}
__device__ __forceinline__ float sig_(float x)  { return 1.0f / (1.0f + __expf(-x)); }
__device__ __forceinline__ float tanh_(float x) { return 2.0f / (1.0f + __expf(-2.0f * x)) - 1.0f; }

__device__ __forceinline__ void split8(const float* v, uint32_t* hp, uint32_t* lp) {
    #pragma unroll
    for (int jj = 0; jj < 4; ++jj) {
        __nv_bfloat16 h0 = __float2bfloat16(v[2 * jj]);
        __nv_bfloat16 h1 = __float2bfloat16(v[2 * jj + 1]);
        __nv_bfloat16 l0 = __float2bfloat16(v[2 * jj]     - __bfloat162float(h0));
        __nv_bfloat16 l1 = __float2bfloat16(v[2 * jj + 1] - __bfloat162float(h1));
        hp[jj] = (uint32_t)__bfloat16_as_ushort(h0) | ((uint32_t)__bfloat16_as_ushort(h1) << 16);
        lp[jj] = (uint32_t)__bfloat16_as_ushort(l0) | ((uint32_t)__bfloat16_as_ushort(l1) << 16);
    }
}

/* Precompute B hi/lo swizzled smem images. 192 threads: (dy, n). */
__global__ void build_B_kernel(const float* __restrict__ Wc)
{
    const int tid = threadIdx.x;
    if (tid >= 192) return;
    const int dy = tid >> 6;
    const int n  = tid & 63;
    #pragma unroll
    for (int i = 0; i < 8; ++i) {
        float v[8];
        #pragma unroll
        for (int j = 0; j < 8; ++j) {
            const int k  = i * 8 + j;
            const int ch = k / 3;
            const int dx = k - ch * 3;
            v[j] = (ch < 21) ? Wc[n * 189 + ch * 9 + dy * 3 + dx] : 0.0f;
        }
        uint32_t hp[4], lp[4];
        split8(v, hp, lp);
        uint32_t off = (uint32_t)(n * 128 + i * 16);
        off ^= (uint32_t)((n & 7) << 4);
        const int idx = (dy * 8192 + (int)off) >> 4;
        g_Bh[idx] = make_uint4(hp[0], hp[1], hp[2], hp[3]);
        g_Bl[idx] = make_uint4(lp[0], lp[1], lp[2], lp[3]);
    }
}

/* Fused ConvLSTM step, bf16 mma.sync implicit GEMM.
   CTA: (b, y0=2*by, x0) -> 2 output rows x 128 px (M=256).
   A tile = 4 input-row strips (y0-1..y0+2); pass dy = base offset dy*16384.
   16 warps = 8(m) x 2(n), warp tile 32x32. 3 comp passes share A/B ldsm. */
__global__ void __launch_bounds__(NTHREADS)
lstm_step_kernel(const float* __restrict__ xall, const float* __restrict__ bc, int t)
{
    extern __shared__ char smem[];
    const uint32_t sb = smem_u32(smem);
    float* s_stage = (float*)smem;

    const int tid  = threadIdx.x;
    const int wid  = tid >> 5;
    const int lane = tid & 31;
    const int b  = blockIdx.z;
    const int y0 = blockIdx.y << 1;
    const int x0 = blockIdx.x << 7;
    const int first = (t == 0);

    const float* h_prev = g_h[t & 1];
    float*       h_next = g_h[(t + 1) & 1];

    /* ---- copy B images (48 KB) ---- */
    {
        uint4* dstH = (uint4*)(smem + SM_BH(0));
        uint4* dstL = (uint4*)(smem + SM_BL(0));
        #pragma unroll 1
        for (int i = tid; i < 1536; i += NTHREADS) { dstH[i] = g_Bh[i]; dstL[i] = g_Bl[i]; }
    }
    /* ---- build A hi/lo: one (strip, px) item per thread ---- */
    {
        const int r  = tid >> 7;            /* input strip 0..3 */
        const int m  = tid & 127;
        const int gy = y0 - 1 + r;
        const bool rowok = ((unsigned)gy < IMG);
        const float* xrow = xall + ((((b * TSTEPS + t) * CIN_X) << 16) + (gy << 8));
        const float* hrow = h_prev + (((b * HID) << 16) + (gy << 8));
        const int xb = x0 + m - 1;
        #pragma unroll
        for (int i = 0; i < 8; ++i) {
            float v[8];
            #pragma unroll
            for (int j = 0; j < 8; ++j) {
                const int k  = i * 8 + j;
                const int ch = k / 3;
                const int dx = k - ch * 3;
                float val = 0.0f;
                if (ch < 21) {
                    const int gx = xb + dx;
                    const bool hload = (ch >= CIN_X);
                    if (rowok && (unsigned)gx < IMG && !(first && hload))
                        val = hload ? hrow[((ch - CIN_X) << 16) + gx]
                                    : xrow[(ch << 16) + gx];
                }
                v[j] = val;
            }
            uint32_t hp[4], lp[4];
            split8(v, hp, lp);
            uint32_t off = (uint32_t)(tid * 128 + i * 16);   /* A row index == tid */
            off ^= (uint32_t)((tid & 7) << 4);
            *(uint4*)(smem + SM_AH + off) = make_uint4(hp[0], hp[1], hp[2], hp[3]);
            *(uint4*)(smem + SM_AL + off) = make_uint4(lp[0], lp[1], lp[2], lp[3]);
        }
    }
    __syncthreads();

    /* ---- mainloop ---- */
    const int wm = wid >> 1;            /* 0..7 -> m_base = wm*32 */
    const int wn = wid & 1;             /* 0..1 -> n_base = wn*32 */
    const int m_base = wm * 32;
    const int n_base = wn * 32;
    const int j  = lane >> 3;
    const int rr = lane & 7;

    uint32_t offA[2], offB[2];
    #pragma unroll
    for (int mt = 0; mt < 2; ++mt) {
        const int row = m_base + mt * 16 + (j & 1) * 8 + rr;
        const int c16 = j >> 1;
        offA[mt] = (uint32_t)(row * 128 + ((c16 << 4) ^ ((row & 7) << 4)));
    }
    #pragma unroll
    for (int nb = 0; nb < 2; ++nb) {
        const int row = n_base + nb * 16 + (j >> 1) * 8 + rr;
        const int c16 = j & 1;
        offB[nb] = (uint32_t)(row * 128 + ((c16 << 4) ^ ((row & 7) << 4)));
    }

    float acc[8][4];
    #pragma unroll
    for (int q = 0; q < 8; ++q)
        #pragma unroll
        for (int e = 0; e < 4; ++e) acc[q][e] = 0.0f;

    #pragma unroll 1
    for (int dy = 0; dy < 3; ++dy) {
        const uint32_t Ahb = sb + SM_AH + (uint32_t)(dy * 16384);
        const uint32_t Alb = sb + SM_AL + (uint32_t)(dy * 16384);
        const uint32_t Bhb = sb + SM_BH(dy);
        const uint32_t Blb = sb + SM_BL(dy);
        #pragma unroll
        for (int kc = 0; kc < 4; ++kc) {
            const uint32_t kx = (uint32_t)(kc << 5);
            uint32_t ah0[4], ah1[4], al0[4], al1[4];
            uint32_t bh0[4], bh1[4], bl0[4], bl1[4];
            ldsm4(ah0, Ahb + (offA[0] ^ kx));
            ldsm4(ah1, Ahb + (offA[1] ^ kx));
            ldsm4(bh0, Bhb + (offB[0] ^ kx));
            ldsm4(bh1, Bhb + (offB[1] ^ kx));
            ldsm4(al0, Alb + (offA[0] ^ kx));
            ldsm4(al1, Alb + (offA[1] ^ kx));
            ldsm4(bl0, Blb + (offB[0] ^ kx));
            ldsm4(bl1, Blb + (offB[1] ^ kx));
            /* hi*hi */
            mma16816(acc[0], ah0, bh0[0], bh0[1]);
            mma16816(acc[1], ah0, bh0[2], bh0[3]);
            mma16816(acc[2], ah0, bh1[0], bh1[1]);
            mma16816(acc[3], ah0, bh1[2], bh1[3]);
            mma16816(acc[4], ah1, bh0[0], bh0[1]);
            mma16816(acc[5], ah1, bh0[2], bh0[3]);
            mma16816(acc[6], ah1, bh1[0], bh1[1]);
            mma16816(acc[7], ah1, bh1[2], bh1[3]);
            /* lo*hi */
            mma16816(acc[0], al0, bh0[0], bh0[1]);
            mma16816(acc[1], al0, bh0[2], bh0[3]);
            mma16816(acc[2], al0, bh1[0], bh1[1]);
            mma16816(acc[3], al0, bh1[2], bh1[3]);
            mma16816(acc[4], al1, bh0[0], bh0[1]);
            mma16816(acc[5], al1, bh0[2], bh0[3]);
            mma16816(acc[6], al1, bh1[0], bh1[1]);
            mma16816(acc[7], al1, bh1[2], bh1[3]);
            /* hi*lo */
            mma16816(acc[0], ah0, bl0[0], bl0[1]);
            mma16816(acc[1], ah0, bl0[2], bl0[3]);
            mma16816(acc[2], ah0, bl1[0], bl1[1]);
            mma16816(acc[3], ah0, bl1[2], bl1[3]);
            mma16816(acc[4], ah1, bl0[0], bl0[1]);
            mma16816(acc[5], ah1, bl0[2], bl0[3]);
            mma16816(acc[6], ah1, bl1[0], bl1[1]);
            mma16816(acc[7], ah1, bl1[2], bl1[3]);
        }
    }
    __syncthreads();

    /* ---- stage acc -> smem f32 [256][66] ---- */
    {
        const int g = lane >> 2;
        const int q = lane & 3;
        #pragma unroll
        for (int mt = 0; mt < 2; ++mt)
            #pragma unroll
            for (int nb = 0; nb < 4; ++nb) {
                const int m = m_base + mt * 16 + g;
                const int n = n_base + nb * 8 + 2 * q;
                float* p0 = s_stage + m * STAGE_STRIDE + n;
                p0[0] = acc[mt * 4 + nb][0];
                p0[1] = acc[mt * 4 + nb][1];
                float* p1 = p0 + 8 * STAGE_STRIDE;
                p1[0] = acc[mt * 4 + nb][2];
                p1[1] = acc[mt * 4 + nb][3];
            }
    }
    __syncthreads();

    /* ---- epilogue: gates + state update, thread = pixel (256 px) ---- */
    if (tid < 256) {
        const float* sp = s_stage + tid * STAGE_STRIDE;
        const int pix = ((y0 + (tid >> 7)) << 8) + x0 + (tid & 127);
        #pragma unroll
        for (int hid = 0; hid < HID; ++hid) {
            const float iv = sp[hid]      + bc[hid];
            const float fv = sp[hid + 16] + bc[hid + 16];
            const float ov = sp[hid + 32] + bc[hid + 32];
            const float gv = sp[hid + 48] + bc[hid + 48];
            const int idx = ((b * HID + hid) << 16) + pix;
            const float cold = first ? 0.0f : g_c[idx];
            const float i = sig_(iv), f = sig_(fv), o = sig_(ov), g = tanh_(gv);
            const float c = f * cold + i * g;
            g_c[idx]    = c;
            h_next[idx] = o * tanh_(c);
        }
    }
}

/* Final 1x1 conv over h_last (g_h[0] after 12 steps). */
__global__ void final_conv_kernel(const float* __restrict__ Wf,
                                  const float* __restrict__ bfin,
                                  float* __restrict__ out)
{
    const int total4 = BATCH * IMG * IMG / 4;
    int idx4 = blockIdx.x * blockDim.x + threadIdx.x;
    if (idx4 >= total4) return;
    const float* h = g_h[TSTEPS & 1];
    int b    = idx4 >> 14;
    int pix4 = idx4 & 16383;
    float w[HID];
    #pragma unroll
    for (int jj = 0; jj < HID; ++jj) w[jj] = Wf[jj];
    float bv = bfin[0];
    float4 a; a.x = bv; a.y = bv; a.z = bv; a.w = bv;
    #pragma unroll
    for (int jj = 0; jj < HID; ++jj) {
        float4 v = *(const float4*)(h + ((b * HID + jj) << 16) + pix4 * 4);
        a.x += w[jj] * v.x; a.y += w[jj] * v.y;
        a.z += w[jj] * v.z; a.w += w[jj] * v.w;
    }
    ((float4*)out)[idx4] = a;
}

extern "C" void kernel_launch(void* const* d_in, const int* in_sizes, int n_in,
                              void* d_out, int out_size)
{
    const float* x  = (const float*)d_in[0];
    const float* Wc = (const float*)d_in[1];
    const float* bc = (const float*)d_in[2];
    const float* Wf = (const float*)d_in[3];
    const float* bf = (const float*)d_in[4];
    float* out = (float*)d_out;

    cudaFuncSetAttribute(lstm_step_kernel,
                         cudaFuncAttributeMaxDynamicSharedMemorySize, SMEM_TOTAL);

    build_B_kernel<<<1, 192>>>(Wc);

    dim3 grid(IMG / 128, IMG / 2, BATCH);   /* (2, 128, 8) = 2048 CTAs */
    for (int t = 0; t < TSTEPS; ++t)
        lstm_step_kernel<<<grid, NTHREADS, SMEM_TOTAL>>>(x, bc, t);

    const int total4 = BATCH * IMG * IMG / 4;
    final_conv_kernel<<<(total4 + 255) / 256, 256>>>(Wf, bf, out);
}

// round 10
// speedup vs baseline: 1.8445x; 1.0322x over previous
#include <cuda_runtime.h>
#include <cuda_bf16.h>
#include <cstdint>

#define BATCH   8
#define TSTEPS  12
#define CIN_X   5
#define HID     16
#define IMG     256
#define NTHREADS 512

/* smem byte offsets (as R9) */
#define SM_AH      0
#define SM_AL      65536
#define SM_BH(dy)  (131072 + (dy) * 8192)
#define SM_BL(dy)  (155648 + (dy) * 8192)
#define SMEM_TOTAL 180224
#define STAGE_STRIDE 66

/* packed (hi<<16)|lo planes */
__device__ uint32_t g_hp[2][BATCH * HID * IMG * IMG];
__device__ uint32_t g_xp[BATCH * TSTEPS * CIN_X * IMG * IMG];
__device__ float    g_c [BATCH * HID * IMG * IMG];
__device__ uint4 g_Bh[3 * 512];
__device__ uint4 g_Bl[3 * 512];

__device__ __forceinline__ uint32_t smem_u32(const void* p) {
    uint32_t a;
    asm("{ .reg .u64 t; cvta.to.shared.u64 t, %1; cvt.u32.u64 %0, t; }" : "=r"(a) : "l"(p));
    return a;
}
__device__ __forceinline__ void ldsm4(uint32_t* r, uint32_t addr) {
    asm volatile("ldmatrix.sync.aligned.m8n8.x4.shared.b16 {%0,%1,%2,%3}, [%4];"
                 : "=r"(r[0]), "=r"(r[1]), "=r"(r[2]), "=r"(r[3]) : "r"(addr));
}
__device__ __forceinline__ void mma16816(float* c, const uint32_t* a, uint32_t b0, uint32_t b1) {
    asm volatile("mma.sync.aligned.m16n8k16.row.col.f32.bf16.bf16.f32 "
                 "{%0,%1,%2,%3}, {%4,%5,%6,%7}, {%8,%9}, {%0,%1,%2,%3};"
                 : "+f"(c[0]), "+f"(c[1]), "+f"(c[2]), "+f"(c[3])
                 : "r"(a[0]), "r"(a[1]), "r"(a[2]), "r"(a[3]), "r"(b0), "r"(b1));
}
__device__ __forceinline__ float sig_(float x)  { return 1.0f / (1.0f + __expf(-x)); }
__device__ __forceinline__ float tanh_(float x) { return 2.0f / (1.0f + __expf(-2.0f * x)) - 1.0f; }

__device__ __forceinline__ uint32_t pack_split(float f) {
    __nv_bfloat16 hi = __float2bfloat16(f);
    __nv_bfloat16 lo = __float2bfloat16(f - __bfloat162float(hi));
    return ((uint32_t)__bfloat16_as_ushort(hi) << 16) | (uint32_t)__bfloat16_as_ushort(lo);
}
__device__ __forceinline__ float unpack_sum(uint32_t r) {
    __nv_bfloat16 hi = __ushort_as_bfloat16((unsigned short)(r >> 16));
    __nv_bfloat16 lo = __ushort_as_bfloat16((unsigned short)(r & 0xFFFF));
    return __bfloat162float(hi) + __bfloat162float(lo);
}

/* ---- prep: x fp32 -> packed planes (once per launch) ---- */
__global__ void prep_x_kernel(const float* __restrict__ x)
{
    const int total4 = BATCH * TSTEPS * CIN_X * IMG * IMG / 4;
    int i = blockIdx.x * blockDim.x + threadIdx.x;
    if (i >= total4) return;
    float4 v = ((const float4*)x)[i];
    uint4 o;
    o.x = pack_split(v.x); o.y = pack_split(v.y);
    o.z = pack_split(v.z); o.w = pack_split(v.w);
    ((uint4*)g_xp)[i] = o;
}

__device__ __forceinline__ void split8(const float* v, uint32_t* hp, uint32_t* lp) {
    #pragma unroll
    for (int jj = 0; jj < 4; ++jj) {
        __nv_bfloat16 h0 = __float2bfloat16(v[2 * jj]);
        __nv_bfloat16 h1 = __float2bfloat16(v[2 * jj + 1]);
        __nv_bfloat16 l0 = __float2bfloat16(v[2 * jj]     - __bfloat162float(h0));
        __nv_bfloat16 l1 = __float2bfloat16(v[2 * jj + 1] - __bfloat162float(h1));
        hp[jj] = (uint32_t)__bfloat16_as_ushort(h0) | ((uint32_t)__bfloat16_as_ushort(h1) << 16);
        lp[jj] = (uint32_t)__bfloat16_as_ushort(l0) | ((uint32_t)__bfloat16_as_ushort(l1) << 16);
    }
}

/* Precompute B hi/lo swizzled smem images. 192 threads: (dy, n). */
__global__ void build_B_kernel(const float* __restrict__ Wc)
{
    const int tid = threadIdx.x;
    if (tid >= 192) return;
    const int dy = tid >> 6;
    const int n  = tid & 63;
    #pragma unroll
    for (int i = 0; i < 8; ++i) {
        float v[8];
        #pragma unroll
        for (int j = 0; j < 8; ++j) {
            const int k  = i * 8 + j;
            const int ch = k / 3;
            const int dx = k - ch * 3;
            v[j] = (ch < 21) ? Wc[n * 189 + ch * 9 + dy * 3 + dx] : 0.0f;
        }
        uint32_t hp[4], lp[4];
        split8(v, hp, lp);
        uint32_t off = (uint32_t)(n * 128 + i * 16);
        off ^= (uint32_t)((n & 7) << 4);
        const int idx = (dy * 8192 + (int)off) >> 4;
        g_Bh[idx] = make_uint4(hp[0], hp[1], hp[2], hp[3]);
        g_Bl[idx] = make_uint4(lp[0], lp[1], lp[2], lp[3]);
    }
}

/* Fused ConvLSTM step, bf16 mma.sync implicit GEMM, software-pipelined.
   CTA: (b, y0=2*by, x0) -> 2 output rows x 128 px (M=256). 16 warps (8m x 2n). */
__global__ void __launch_bounds__(NTHREADS)
lstm_step_kernel(const float* __restrict__ bc, int t)
{
    extern __shared__ char smem[];
    const uint32_t sb = smem_u32(smem);
    float* s_stage = (float*)smem;

    const int tid  = threadIdx.x;
    const int wid  = tid >> 5;
    const int lane = tid & 31;
    const int b  = blockIdx.z;
    const int y0 = blockIdx.y << 1;
    const int x0 = blockIdx.x << 7;
    const int first = (t == 0);

    const uint32_t* hp_prev = g_hp[t & 1];
    uint32_t*       hp_next = g_hp[(t + 1) & 1];

    /* ---- copy B images (48 KB) ---- */
    {
        uint4* dstH = (uint4*)(smem + SM_BH(0));
        uint4* dstL = (uint4*)(smem + SM_BL(0));
        #pragma unroll 1
        for (int i = tid; i < 1536; i += NTHREADS) { dstH[i] = g_Bh[i]; dstL[i] = g_Bl[i]; }
    }
    /* ---- build A hi/lo from packed planes: (strip, px) per thread ---- */
    {
        const int r  = tid >> 7;
        const int m  = tid & 127;
        const int gy = y0 - 1 + r;
        const bool rowok = ((unsigned)gy < IMG);
        const uint32_t* xrow = g_xp + ((((b * TSTEPS + t) * CIN_X) << 16) + (gy << 8));
        const uint32_t* hrow = hp_prev + (((b * HID) << 16) + (gy << 8));
        const int xb = x0 + m - 1;
        #pragma unroll
        for (int i = 0; i < 8; ++i) {
            uint32_t rv[8];
            #pragma unroll
            for (int j = 0; j < 8; ++j) {
                const int k  = i * 8 + j;
                uint32_t val = 0u;
                if (k < 63) {
                    const int ch = k / 3;
                    const int dx = k - ch * 3;
                    const int gx = xb + dx;
                    const bool hload = (ch >= CIN_X);
                    if (rowok && (unsigned)gx < IMG && !(first && hload))
                        val = hload ? hrow[((ch - CIN_X) << 16) + gx]
                                    : xrow[(ch << 16) + gx];
                }
                rv[j] = val;
            }
            uint32_t hp[4], lp[4];
            #pragma unroll
            for (int jj = 0; jj < 4; ++jj) {
                /* packed = (hi<<16)|lo; bf16x2 pair: low half = even elem */
                hp[jj] = __byte_perm(rv[2 * jj], rv[2 * jj + 1], 0x7632);
                lp[jj] = __byte_perm(rv[2 * jj], rv[2 * jj + 1], 0x5410);
            }
            uint32_t off = (uint32_t)(tid * 128 + i * 16);
            off ^= (uint32_t)((tid & 7) << 4);
            *(uint4*)(smem + SM_AH + off) = make_uint4(hp[0], hp[1], hp[2], hp[3]);
            *(uint4*)(smem + SM_AL + off) = make_uint4(lp[0], lp[1], lp[2], lp[3]);
        }
    }
    __syncthreads();

    /* ---- mainloop (double-banked software pipeline) ---- */
    const int wm = wid >> 1;
    const int wn = wid & 1;
    const int m_base = wm * 32;
    const int n_base = wn * 32;
    const int j  = lane >> 3;
    const int rr = lane & 7;

    uint32_t offA[2], offB[2];
    #pragma unroll
    for (int mt = 0; mt < 2; ++mt) {
        const int row = m_base + mt * 16 + (j & 1) * 8 + rr;
        const int c16 = j >> 1;
        offA[mt] = (uint32_t)(row * 128 + ((c16 << 4) ^ ((row & 7) << 4)));
    }
    #pragma unroll
    for (int nb = 0; nb < 2; ++nb) {
        const int row = n_base + nb * 16 + (j >> 1) * 8 + rr;
        const int c16 = j & 1;
        offB[nb] = (uint32_t)(row * 128 + ((c16 << 4) ^ ((row & 7) << 4)));
    }

    float acc[8][4];
    #pragma unroll
    for (int q = 0; q < 8; ++q)
        #pragma unroll
        for (int e = 0; e < 4; ++e) acc[q][e] = 0.0f;

    /* frag[bank][0..7]: ah0 ah1 al0 al1 bh0 bh1 bl0 bl1 */
    uint32_t frag[2][8][4];

    #define LOAD_ITER(it, bank)                                                   \
        do {                                                                      \
            const int _dy = (it) >> 2;                                            \
            const uint32_t _kx = (uint32_t)(((it) & 3) << 5);                     \
            const uint32_t _Ah = sb + SM_AH + (uint32_t)(_dy * 16384);            \
            const uint32_t _Al = sb + SM_AL + (uint32_t)(_dy * 16384);            \
            const uint32_t _Bh = sb + SM_BH(_dy);                                 \
            const uint32_t _Bl = sb + SM_BL(_dy);                                 \
            ldsm4(frag[bank][0], _Ah + (offA[0] ^ _kx));                          \
            ldsm4(frag[bank][1], _Ah + (offA[1] ^ _kx));                          \
            ldsm4(frag[bank][2], _Al + (offA[0] ^ _kx));                          \
            ldsm4(frag[bank][3], _Al + (offA[1] ^ _kx));                          \
            ldsm4(frag[bank][4], _Bh + (offB[0] ^ _kx));                          \
            ldsm4(frag[bank][5], _Bh + (offB[1] ^ _kx));                          \
            ldsm4(frag[bank][6], _Bl + (offB[0] ^ _kx));                          \
            ldsm4(frag[bank][7], _Bl + (offB[1] ^ _kx));                          \
        } while (0)

    LOAD_ITER(0, 0);
    #pragma unroll
    for (int it = 0; it < 12; ++it) {
        const int cur = it & 1;
        if (it < 11) LOAD_ITER(it + 1, cur ^ 1);
        const uint32_t (*f)[4] = frag[cur];
        /* hi*hi */
        mma16816(acc[0], f[0], f[4][0], f[4][1]);
        mma16816(acc[1], f[0], f[4][2], f[4][3]);
        mma16816(acc[2], f[0], f[5][0], f[5][1]);
        mma16816(acc[3], f[0], f[5][2], f[5][3]);
        mma16816(acc[4], f[1], f[4][0], f[4][1]);
        mma16816(acc[5], f[1], f[4][2], f[4][3]);
        mma16816(acc[6], f[1], f[5][0], f[5][1]);
        mma16816(acc[7], f[1], f[5][2], f[5][3]);
        /* lo*hi */
        mma16816(acc[0], f[2], f[4][0], f[4][1]);
        mma16816(acc[1], f[2], f[4][2], f[4][3]);
        mma16816(acc[2], f[2], f[5][0], f[5][1]);
        mma16816(acc[3], f[2], f[5][2], f[5][3]);
        mma16816(acc[4], f[3], f[4][0], f[4][1]);
        mma16816(acc[5], f[3], f[4][2], f[4][3]);
        mma16816(acc[6], f[3], f[5][0], f[5][1]);
        mma16816(acc[7], f[3], f[5][2], f[5][3]);
        /* hi*lo */
        mma16816(acc[0], f[0], f[6][0], f[6][1]);
        mma16816(acc[1], f[0], f[6][2], f[6][3]);
        mma16816(acc[2], f[0], f[7][0], f[7][1]);
        mma16816(acc[3], f[0], f[7][2], f[7][3]);
        mma16816(acc[4], f[1], f[6][0], f[6][1]);
        mma16816(acc[5], f[1], f[6][2], f[6][3]);
        mma16816(acc[6], f[1], f[7][0], f[7][1]);
        mma16816(acc[7], f[1], f[7][2], f[7][3]);
    }
    #undef LOAD_ITER
    __syncthreads();

    /* ---- stage acc -> smem f32 [256][66] ---- */
    {
        const int g = lane >> 2;
        const int q = lane & 3;
        #pragma unroll
        for (int mt = 0; mt < 2; ++mt)
            #pragma unroll
            for (int nb = 0; nb < 4; ++nb) {
                const int m = m_base + mt * 16 + g;
                const int n = n_base + nb * 8 + 2 * q;
                float* p0 = s_stage + m * STAGE_STRIDE + n;
                p0[0] = acc[mt * 4 + nb][0];
                p0[1] = acc[mt * 4 + nb][1];
                float* p1 = p0 + 8 * STAGE_STRIDE;
                p1[0] = acc[mt * 4 + nb][2];
                p1[1] = acc[mt * 4 + nb][3];
            }
    }
    __syncthreads();

    /* ---- epilogue: gates + state; h written as packed hi/lo ---- */
    if (tid < 256) {
        const float* sp = s_stage + tid * STAGE_STRIDE;
        const int pix = ((y0 + (tid >> 7)) << 8) + x0 + (tid & 127);
        #pragma unroll
        for (int hid = 0; hid < HID; ++hid) {
            const float iv = sp[hid]      + bc[hid];
            const float fv = sp[hid + 16] + bc[hid + 16];
            const float ov = sp[hid + 32] + bc[hid + 32];
            const float gv = sp[hid + 48] + bc[hid + 48];
            const int idx = ((b * HID + hid) << 16) + pix;
            const float cold = first ? 0.0f : g_c[idx];
            const float i = sig_(iv), f = sig_(fv), o = sig_(ov), g = tanh_(gv);
            const float c = f * cold + i * g;
            g_c[idx]     = c;
            hp_next[idx] = pack_split(o * tanh_(c));
        }
    }
}

/* Final 1x1 conv over packed h_last (g_hp[0] after 12 steps). */
__global__ void final_conv_kernel(const float* __restrict__ Wf,
                                  const float* __restrict__ bfin,
                                  float* __restrict__ out)
{
    const int total4 = BATCH * IMG * IMG / 4;
    int idx4 = blockIdx.x * blockDim.x + threadIdx.x;
    if (idx4 >= total4) return;
    const uint32_t* h = g_hp[TSTEPS & 1];
    int b    = idx4 >> 14;
    int pix4 = idx4 & 16383;
    float w[HID];
    #pragma unroll
    for (int jj = 0; jj < HID; ++jj) w[jj] = Wf[jj];
    float bv = bfin[0];
    float4 a; a.x = bv; a.y = bv; a.z = bv; a.w = bv;
    #pragma unroll
    for (int jj = 0; jj < HID; ++jj) {
        uint4 v = *(const uint4*)(h + ((b * HID + jj) << 16) + pix4 * 4);
        a.x += w[jj] * unpack_sum(v.x); a.y += w[jj] * unpack_sum(v.y);
        a.z += w[jj] * unpack_sum(v.z); a.w += w[jj] * unpack_sum(v.w);
    }
    ((float4*)out)[idx4] = a;
}

extern "C" void kernel_launch(void* const* d_in, const int* in_sizes, int n_in,
                              void* d_out, int out_size)
{
    const float* x  = (const float*)d_in[0];
    const float* Wc = (const float*)d_in[1];
    const float* bc = (const float*)d_in[2];
    const float* Wf = (const float*)d_in[3];
    const float* bf = (const float*)d_in[4];
    float* out = (float*)d_out;

    cudaFuncSetAttribute(lstm_step_kernel,
                         cudaFuncAttributeMaxDynamicSharedMemorySize, SMEM_TOTAL);

    const int xtotal4 = BATCH * TSTEPS * CIN_X * IMG * IMG / 4;
    prep_x_kernel<<<(xtotal4 + 255) / 256, 256>>>(x);
    build_B_kernel<<<1, 192>>>(Wc);

    dim3 grid(IMG / 128, IMG / 2, BATCH);
    for (int t = 0; t < TSTEPS; ++t)
        lstm_step_kernel<<<grid, NTHREADS, SMEM_TOTAL>>>(bc, t);

    const int total4 = BATCH * IMG * IMG / 4;
    final_conv_kernel<<<(total4 + 255) / 256, 256>>>(Wf, bf, out);
}

// round 12
// speedup vs baseline: 3.6319x; 1.9690x over previous
#include <cuda_runtime.h>
#include <cuda_fp16.h>
#include <cstdint>

#define BATCH   8
#define TSTEPS  12
#define CIN_X   5
#define HID     16
#define IMG     256
#define NTHREADS 512

/* smem byte offsets:
   A (fp16 hi only): [512 rows][64 f16] = 4 input-row strips, 65536 B
   B-hi: 3 dy x 8192 B at 65536..90112
   B-lo: 3 dy x 8192 B at 90112..114688                               */
#define SM_A       0
#define SM_BH(dy)  (65536 + (dy) * 8192)
#define SM_BL(dy)  (90112 + (dy) * 8192)
#define SMEM_TOTAL 114688              /* 112 KB -> 2 CTAs/SM */
#define STAGE_STRIDE 66                /* f32 stage, 256*66*4 = 67584 <= total */

__device__ __half g_hh[2][BATCH * HID * IMG * IMG];   /* h state, fp16 */
__device__ float  g_c [BATCH * HID * IMG * IMG];
__device__ uint4  g_Bh[3 * 512];
__device__ uint4  g_Bl[3 * 512];

__device__ __forceinline__ uint32_t smem_u32(const void* p) {
    uint32_t a;
    asm("{ .reg .u64 t; cvta.to.shared.u64 t, %1; cvt.u32.u64 %0, t; }" : "=r"(a) : "l"(p));
    return a;
}
__device__ __forceinline__ void ldsm4(uint32_t* r, uint32_t addr) {
    asm volatile("ldmatrix.sync.aligned.m8n8.x4.shared.b16 {%0,%1,%2,%3}, [%4];"
                 : "=r"(r[0]), "=r"(r[1]), "=r"(r[2]), "=r"(r[3]) : "r"(addr));
}
__device__ __forceinline__ void mma16816(float* c, const uint32_t* a, uint32_t b0, uint32_t b1) {
    asm volatile("mma.sync.aligned.m16n8k16.row.col.f32.f16.f16.f32 "
                 "{%0,%1,%2,%3}, {%4,%5,%6,%7}, {%8,%9}, {%0,%1,%2,%3};"
                 : "+f"(c[0]), "+f"(c[1]), "+f"(c[2]), "+f"(c[3])
                 : "r"(a[0]), "r"(a[1]), "r"(a[2]), "r"(a[3]), "r"(b0), "r"(b1));
}
__device__ __forceinline__ float sig_(float x)  { return 1.0f / (1.0f + __expf(-x)); }
__device__ __forceinline__ float tanh_(float x) { return 2.0f / (1.0f + __expf(-2.0f * x)) - 1.0f; }

/* Precompute B hi/lo (fp16 split) swizzled smem images. 192 threads: (dy, n). */
__global__ void build_B_kernel(const float* __restrict__ Wc)
{
    const int tid = threadIdx.x;
    if (tid >= 192) return;
    const int dy = tid >> 6;
    const int n  = tid & 63;
    #pragma unroll
    for (int i = 0; i < 8; ++i) {
        uint32_t hp[4], lp[4];
        #pragma unroll
        for (int jj = 0; jj < 4; ++jj) {
            float v0 = 0.0f, v1 = 0.0f;
            {
                const int k = i * 8 + 2 * jj;
                const int ch = k / 3, dx = k - ch * 3;
                if (ch < 21) v0 = Wc[n * 189 + ch * 9 + dy * 3 + dx];
            }
            {
                const int k = i * 8 + 2 * jj + 1;
                const int ch = k / 3, dx = k - ch * 3;
                if (ch < 21) v1 = Wc[n * 189 + ch * 9 + dy * 3 + dx];
            }
            __half h0 = __float2half_rn(v0);
            __half h1 = __float2half_rn(v1);
            __half l0 = __float2half_rn(v0 - __half2float(h0));
            __half l1 = __float2half_rn(v1 - __half2float(h1));
            hp[jj] = (uint32_t)__half_as_ushort(h0) | ((uint32_t)__half_as_ushort(h1) << 16);
            lp[jj] = (uint32_t)__half_as_ushort(l0) | ((uint32_t)__half_as_ushort(l1) << 16);
        }
        uint32_t off = (uint32_t)(n * 128 + i * 16);
        off ^= (uint32_t)((n & 7) << 4);
        const int idx = (dy * 8192 + (int)off) >> 4;
        g_Bh[idx] = make_uint4(hp[0], hp[1], hp[2], hp[3]);
        g_Bl[idx] = make_uint4(lp[0], lp[1], lp[2], lp[3]);
    }
}

/* Fused ConvLSTM step: fp16 mma.sync implicit GEMM, 2-term weight compensation.
   CTA: (b, y0=2*by, x0) -> 2 output rows x 128 px (M=256). 16 warps (8m x 2n).
   2 CTAs/SM: build/epilogue of one CTA overlaps the other's mainloop. */
__global__ void __launch_bounds__(NTHREADS, 2)
lstm_step_kernel(const float* __restrict__ xall, const float* __restrict__ bc, int t)
{
    extern __shared__ char smem[];
    const uint32_t sb = smem_u32(smem);
    float* s_stage = (float*)smem;

    const int tid  = threadIdx.x;
    const int wid  = tid >> 5;
    const int lane = tid & 31;
    const int b  = blockIdx.z;
    const int y0 = blockIdx.y << 1;
    const int x0 = blockIdx.x << 7;
    const int first = (t == 0);

    const __half* hh_prev = g_hh[t & 1];
    __half*       hh_next = g_hh[(t + 1) & 1];

    /* ---- copy B images (48 KB) ---- */
    {
        uint4* dstH = (uint4*)(smem + SM_BH(0));
        uint4* dstL = (uint4*)(smem + SM_BL(0));
        #pragma unroll 1
        for (int i = tid; i < 1536; i += NTHREADS) { dstH[i] = g_Bh[i]; dstL[i] = g_Bl[i]; }
    }
    /* ---- build A (fp16 hi only): one (strip, px) per thread; row = tid ---- */
    {
        const int r  = tid >> 7;            /* input strip 0..3 */
        const int m  = tid & 127;
        const int gy = y0 - 1 + r;
        const bool rowok = ((unsigned)gy < IMG);
        const float*  xrow = xall + ((((b * TSTEPS + t) * CIN_X) << 16) + (gy << 8));
        const __half* hrow = hh_prev + (((b * HID) << 16) + (gy << 8));
        const int xb = x0 + m - 1;
        #pragma unroll
        for (int i = 0; i < 4; ++i) {       /* 4 x 16 taps = 64 (pad k=63) */
            uint32_t hp[8];
            #pragma unroll
            for (int jj = 0; jj < 8; ++jj) {
                unsigned short u0 = 0, u1 = 0;
                #pragma unroll
                for (int e = 0; e < 2; ++e) {
                    const int k = i * 16 + 2 * jj + e;
                    unsigned short us = 0;
                    if (k < 63) {
                        const int ch = k / 3;
                        const int dx = k - ch * 3;
                        const int gx = xb + dx;
                        const bool hload = (ch >= CIN_X);
                        if (rowok && (unsigned)gx < IMG && !(first && hload)) {
                            if (hload)
                                us = __half_as_ushort(hrow[((ch - CIN_X) << 16) + gx]);
                            else
                                us = __half_as_ushort(__float2half_rn(xrow[(ch << 16) + gx]));
                        }
                    }
                    if (e == 0) u0 = us; else u1 = us;
                }
                hp[jj] = (uint32_t)u0 | ((uint32_t)u1 << 16);
            }
            uint32_t off = (uint32_t)(tid * 128 + i * 32);
            off ^= (uint32_t)((tid & 7) << 4);
            *(uint4*)(smem + SM_A + off)      = make_uint4(hp[0], hp[1], hp[2], hp[3]);
            *(uint4*)(smem + SM_A + (off ^ 16)) = make_uint4(hp[4], hp[5], hp[6], hp[7]);
        }
    }
    __syncthreads();

    /* ---- mainloop ---- */
    const int wm = wid >> 1;
    const int wn = wid & 1;
    const int m_base = wm * 32;
    const int n_base = wn * 32;
    const int j  = lane >> 3;
    const int rr = lane & 7;

    uint32_t offA[2], offB[2];
    #pragma unroll
    for (int mt = 0; mt < 2; ++mt) {
        const int row = m_base + mt * 16 + (j & 1) * 8 + rr;
        const int c16 = j >> 1;
        offA[mt] = (uint32_t)(row * 128 + ((c16 << 4) ^ ((row & 7) << 4)));
    }
    #pragma unroll
    for (int nb = 0; nb < 2; ++nb) {
        const int row = n_base + nb * 16 + (j >> 1) * 8 + rr;
        const int c16 = j & 1;
        offB[nb] = (uint32_t)(row * 128 + ((c16 << 4) ^ ((row & 7) << 4)));
    }

    float acc[8][4];
    #pragma unroll
    for (int q = 0; q < 8; ++q)
        #pragma unroll
        for (int e = 0; e < 4; ++e) acc[q][e] = 0.0f;

    #pragma unroll
    for (int it = 0; it < 12; ++it) {
        const int dy = it >> 2;
        const uint32_t kx = (uint32_t)((it & 3) << 5);
        const uint32_t Ab  = sb + SM_A + (uint32_t)(dy * 16384);
        uint32_t a0[4], a1[4], b0[4], b1[4];
        ldsm4(a0, Ab + (offA[0] ^ kx));
        ldsm4(a1, Ab + (offA[1] ^ kx));
        /* pass 1: B-hi */
        ldsm4(b0, sb + SM_BH(dy) + (offB[0] ^ kx));
        ldsm4(b1, sb + SM_BH(dy) + (offB[1] ^ kx));
        mma16816(acc[0], a0, b0[0], b0[1]);
        mma16816(acc[1], a0, b0[2], b0[3]);
        mma16816(acc[2], a0, b1[0], b1[1]);
        mma16816(acc[3], a0, b1[2], b1[3]);
        mma16816(acc[4], a1, b0[0], b0[1]);
        mma16816(acc[5], a1, b0[2], b0[3]);
        mma16816(acc[6], a1, b1[0], b1[1]);
        mma16816(acc[7], a1, b1[2], b1[3]);
        /* pass 2: B-lo */
        ldsm4(b0, sb + SM_BL(dy) + (offB[0] ^ kx));
        ldsm4(b1, sb + SM_BL(dy) + (offB[1] ^ kx));
        mma16816(acc[0], a0, b0[0], b0[1]);
        mma16816(acc[1], a0, b0[2], b0[3]);
        mma16816(acc[2], a0, b1[0], b1[1]);
        mma16816(acc[3], a0, b1[2], b1[3]);
        mma16816(acc[4], a1, b0[0], b0[1]);
        mma16816(acc[5], a1, b0[2], b0[3]);
        mma16816(acc[6], a1, b1[0], b1[1]);
        mma16816(acc[7], a1, b1[2], b1[3]);
    }
    __syncthreads();

    /* ---- stage acc -> smem f32 [256][66] ---- */
    {
        const int g = lane >> 2;
        const int q = lane & 3;
        #pragma unroll
        for (int mt = 0; mt < 2; ++mt)
            #pragma unroll
            for (int nb = 0; nb < 4; ++nb) {
                const int m = m_base + mt * 16 + g;
                const int n = n_base + nb * 8 + 2 * q;
                float* p0 = s_stage + m * STAGE_STRIDE + n;
                p0[0] = acc[mt * 4 + nb][0];
                p0[1] = acc[mt * 4 + nb][1];
                float* p1 = p0 + 8 * STAGE_STRIDE;
                p1[0] = acc[mt * 4 + nb][2];
                p1[1] = acc[mt * 4 + nb][3];
            }
    }
    __syncthreads();

    /* ---- epilogue: gates + state; h written as fp16 ---- */
    if (tid < 256) {
        const float* sp = s_stage + tid * STAGE_STRIDE;
        const int pix = ((y0 + (tid >> 7)) << 8) + x0 + (tid & 127);
        #pragma unroll
        for (int hid = 0; hid < HID; ++hid) {
            const float iv = sp[hid]      + bc[hid];
            const float fv = sp[hid + 16] + bc[hid + 16];
            const float ov = sp[hid + 32] + bc[hid + 32];
            const float gv = sp[hid + 48] + bc[hid + 48];
            const int idx = ((b * HID + hid) << 16) + pix;
            const float cold = first ? 0.0f : g_c[idx];
            const float i = sig_(iv), f = sig_(fv), o = sig_(ov), g = tanh_(gv);
            const float c = f * cold + i * g;
            g_c[idx]     = c;
            hh_next[idx] = __float2half_rn(o * tanh_(c));
        }
    }
}

/* Final 1x1 conv over fp16 h_last (g_hh[0] after 12 steps). 8 px per thread. */
__global__ void final_conv_kernel(const float* __restrict__ Wf,
                                  const float* __restrict__ bfin,
                                  float* __restrict__ out)
{
    const int total8 = BATCH * IMG * IMG / 8;
    int idx8 = blockIdx.x * blockDim.x + threadIdx.x;
    if (idx8 >= total8) return;
    const __half* h = g_hh[TSTEPS & 1];
    int b    = idx8 >> 13;              /* 8192 groups per image */
    int pix8 = idx8 & 8191;
    float w[HID];
    #pragma unroll
    for (int jj = 0; jj < HID; ++jj) w[jj] = Wf[jj];
    float bv = bfin[0];
    float a[8];
    #pragma unroll
    for (int p = 0; p < 8; ++p) a[p] = bv;
    #pragma unroll
    for (int jj = 0; jj < HID; ++jj) {
        const __half* hp = h + ((b * HID + jj) << 16) + pix8 * 8;
        uint4 v = *(const uint4*)hp;
        const __half2* h2 = (const __half2*)&v;
        #pragma unroll
        for (int q = 0; q < 4; ++q) {
            float2 f2 = __half22float2(h2[q]);
            a[2 * q]     += w[jj] * f2.x;
            a[2 * q + 1] += w[jj] * f2.y;
        }
    }
    float4* o = (float4*)(out + ((b << 16) + pix8 * 8));
    o[0] = make_float4(a[0], a[1], a[2], a[3]);
    o[1] = make_float4(a[4], a[5], a[6], a[7]);
}

extern "C" void kernel_launch(void* const* d_in, const int* in_sizes, int n_in,
                              void* d_out, int out_size)
{
    const float* x  = (const float*)d_in[0];
    const float* Wc = (const float*)d_in[1];
    const float* bc = (const float*)d_in[2];
    const float* Wf = (const float*)d_in[3];
    const float* bf = (const float*)d_in[4];
    float* out = (float*)d_out;

    cudaFuncSetAttribute(lstm_step_kernel,
                         cudaFuncAttributeMaxDynamicSharedMemorySize, SMEM_TOTAL);

    build_B_kernel<<<1, 192>>>(Wc);

    dim3 grid(IMG / 128, IMG / 2, BATCH);   /* 2048 CTAs */
    for (int t = 0; t < TSTEPS; ++t)
        lstm_step_kernel<<<grid, NTHREADS, SMEM_TOTAL>>>(x, bc, t);

    const int total8 = BATCH * IMG * IMG / 8;
    final_conv_kernel<<<(total8 + 255) / 256, 256>>>(Wf, bf, out);
}

// round 14
// speedup vs baseline: 4.2281x; 1.1642x over previous
#include <cuda_runtime.h>
#include <cuda_fp16.h>
#include <cstdint>

#define BATCH   8
#define TSTEPS  12
#define CIN_X   5
#define HID     16
#define IMG     256
#define NTHREADS 512

/* smem byte offsets:
   A (fp16): [512 rows][64 f16] = 4 input-row strips, 65536 B
   B (fp16): 3 dy x 8192 B at 65536..90112                            */
#define SM_A       0
#define SM_B(dy)   (65536 + (dy) * 8192)
#define SMEM_TOTAL 90112               /* 88 KB -> 2 CTAs/SM */
#define STAGE_STRIDE 66                /* f32 stage: 256*66*4 = 67584 <= total */

__device__ __half g_hh[2][BATCH * HID * IMG * IMG];   /* h state, fp16 */
__device__ float  g_c [BATCH * HID * IMG * IMG];
__device__ uint4  g_B [3 * 512];

__device__ __forceinline__ uint32_t smem_u32(const void* p) {
    uint32_t a;
    asm("{ .reg .u64 t; cvta.to.shared.u64 t, %1; cvt.u32.u64 %0, t; }" : "=r"(a) : "l"(p));
    return a;
}
__device__ __forceinline__ void ldsm4(uint32_t* r, uint32_t addr) {
    asm volatile("ldmatrix.sync.aligned.m8n8.x4.shared.b16 {%0,%1,%2,%3}, [%4];"
                 : "=r"(r[0]), "=r"(r[1]), "=r"(r[2]), "=r"(r[3]) : "r"(addr));
}
__device__ __forceinline__ void mma16816(float* c, const uint32_t* a, uint32_t b0, uint32_t b1) {
    asm volatile("mma.sync.aligned.m16n8k16.row.col.f32.f16.f16.f32 "
                 "{%0,%1,%2,%3}, {%4,%5,%6,%7}, {%8,%9}, {%0,%1,%2,%3};"
                 : "+f"(c[0]), "+f"(c[1]), "+f"(c[2]), "+f"(c[3])
                 : "r"(a[0]), "r"(a[1]), "r"(a[2]), "r"(a[3]), "r"(b0), "r"(b1));
}
__device__ __forceinline__ float sig_(float x)  { return 1.0f / (1.0f + __expf(-x)); }
__device__ __forceinline__ float tanh_(float x) { return 2.0f / (1.0f + __expf(-2.0f * x)) - 1.0f; }

/* Precompute B (fp16) swizzled smem image. 192 threads: (dy, n). */
__global__ void build_B_kernel(const float* __restrict__ Wc)
{
    const int tid = threadIdx.x;
    if (tid >= 192) return;
    const int dy = tid >> 6;
    const int n  = tid & 63;
    #pragma unroll
    for (int i = 0; i < 8; ++i) {
        uint32_t hp[4];
        #pragma unroll
        for (int jj = 0; jj < 4; ++jj) {
            float v0 = 0.0f, v1 = 0.0f;
            {
                const int k = i * 8 + 2 * jj;
                const int ch = k / 3, dx = k - ch * 3;
                if (ch < 21) v0 = Wc[n * 189 + ch * 9 + dy * 3 + dx];
            }
            {
                const int k = i * 8 + 2 * jj + 1;
                const int ch = k / 3, dx = k - ch * 3;
                if (ch < 21) v1 = Wc[n * 189 + ch * 9 + dy * 3 + dx];
            }
            hp[jj] = (uint32_t)__half_as_ushort(__float2half_rn(v0)) |
                     ((uint32_t)__half_as_ushort(__float2half_rn(v1)) << 16);
        }
        uint32_t off = (uint32_t)(n * 128 + i * 16);
        off ^= (uint32_t)((n & 7) << 4);
        g_B[(dy * 8192 + (int)off) >> 4] = make_uint4(hp[0], hp[1], hp[2], hp[3]);
    }
}

/* Fused ConvLSTM step: single-pass fp16 mma.sync implicit GEMM.
   CTA: (b, y0=2*by, x0) -> 2 output rows x 128 px (M=256). 16 warps (8m x 2n).
   2 CTAs/SM: build/epilogue of one CTA overlaps the other's mainloop. */
__global__ void __launch_bounds__(NTHREADS, 2)
lstm_step_kernel(const float* __restrict__ xall, const float* __restrict__ bc, int t)
{
    extern __shared__ char smem[];
    const uint32_t sb = smem_u32(smem);
    float* s_stage = (float*)smem;

    const int tid  = threadIdx.x;
    const int wid  = tid >> 5;
    const int lane = tid & 31;
    const int b  = blockIdx.z;
    const int y0 = blockIdx.y << 1;
    const int x0 = blockIdx.x << 7;
    const int first = (t == 0);

    const __half* hh_prev = g_hh[t & 1];
    __half*       hh_next = g_hh[(t + 1) & 1];

    /* ---- copy B image (24 KB) ---- */
    {
        uint4* dst = (uint4*)(smem + SM_B(0));
        #pragma unroll 1
        for (int i = tid; i < 1536; i += NTHREADS) dst[i] = g_B[i];
    }
    /* ---- build A (fp16): one (strip, px) per thread; A row = tid ---- */
    {
        const int r  = tid >> 7;            /* input strip 0..3 */
        const int m  = tid & 127;
        const int gy = y0 - 1 + r;
        const bool rowok = ((unsigned)gy < IMG);
        const float*  xrow = xall + ((((b * TSTEPS + t) * CIN_X) << 16) + (gy << 8));
        const __half* hrow = hh_prev + (((b * HID) << 16) + (gy << 8));
        const int xb = x0 + m - 1;
        #pragma unroll
        for (int i = 0; i < 4; ++i) {       /* 4 x 16 taps = 64 (pad k=63) */
            uint32_t hp[8];
            #pragma unroll
            for (int jj = 0; jj < 8; ++jj) {
                unsigned short u0 = 0, u1 = 0;
                #pragma unroll
                for (int e = 0; e < 2; ++e) {
                    const int k = i * 16 + 2 * jj + e;
                    unsigned short us = 0;
                    if (k < 63) {
                        const int ch = k / 3;
                        const int dx = k - ch * 3;
                        const int gx = xb + dx;
                        const bool hload = (ch >= CIN_X);
                        if (rowok && (unsigned)gx < IMG && !(first && hload)) {
                            if (hload)
                                us = __half_as_ushort(hrow[((ch - CIN_X) << 16) + gx]);
                            else
                                us = __half_as_ushort(__float2half_rn(xrow[(ch << 16) + gx]));
                        }
                    }
                    if (e == 0) u0 = us; else u1 = us;
                }
                hp[jj] = (uint32_t)u0 | ((uint32_t)u1 << 16);
            }
            uint32_t off = (uint32_t)(tid * 128 + i * 32);
            off ^= (uint32_t)((tid & 7) << 4);
            *(uint4*)(smem + SM_A + off)        = make_uint4(hp[0], hp[1], hp[2], hp[3]);
            *(uint4*)(smem + SM_A + (off ^ 16)) = make_uint4(hp[4], hp[5], hp[6], hp[7]);
        }
    }
    __syncthreads();

    /* ---- mainloop: 12 iters x (4 ldsm + 8 mma) ---- */
    const int wm = wid >> 1;
    const int wn = wid & 1;
    const int m_base = wm * 32;
    const int n_base = wn * 32;
    const int j  = lane >> 3;
    const int rr = lane & 7;

    uint32_t offA[2], offB[2];
    #pragma unroll
    for (int mt = 0; mt < 2; ++mt) {
        const int row = m_base + mt * 16 + (j & 1) * 8 + rr;
        const int c16 = j >> 1;
        offA[mt] = (uint32_t)(row * 128 + ((c16 << 4) ^ ((row & 7) << 4)));
    }
    #pragma unroll
    for (int nb = 0; nb < 2; ++nb) {
        const int row = n_base + nb * 16 + (j >> 1) * 8 + rr;
        const int c16 = j & 1;
        offB[nb] = (uint32_t)(row * 128 + ((c16 << 4) ^ ((row & 7) << 4)));
    }

    float acc[8][4];
    #pragma unroll
    for (int q = 0; q < 8; ++q)
        #pragma unroll
        for (int e = 0; e < 4; ++e) acc[q][e] = 0.0f;

    #pragma unroll
    for (int it = 0; it < 12; ++it) {
        const int dy = it >> 2;
        const uint32_t kx = (uint32_t)((it & 3) << 5);
        const uint32_t Ab = sb + SM_A + (uint32_t)(dy * 16384);
        uint32_t a0[4], a1[4], b0[4], b1[4];
        ldsm4(a0, Ab + (offA[0] ^ kx));
        ldsm4(a1, Ab + (offA[1] ^ kx));
        ldsm4(b0, sb + SM_B(dy) + (offB[0] ^ kx));
        ldsm4(b1, sb + SM_B(dy) + (offB[1] ^ kx));
        mma16816(acc[0], a0, b0[0], b0[1]);
        mma16816(acc[1], a0, b0[2], b0[3]);
        mma16816(acc[2], a0, b1[0], b1[1]);
        mma16816(acc[3], a0, b1[2], b1[3]);
        mma16816(acc[4], a1, b0[0], b0[1]);
        mma16816(acc[5], a1, b0[2], b0[3]);
        mma16816(acc[6], a1, b1[0], b1[1]);
        mma16816(acc[7], a1, b1[2], b1[3]);
    }
    __syncthreads();

    /* ---- stage acc -> smem f32 [256][66] (overwrites A/B regions) ---- */
    {
        const int g = lane >> 2;
        const int q = lane & 3;
        #pragma unroll
        for (int mt = 0; mt < 2; ++mt)
            #pragma unroll
            for (int nb = 0; nb < 4; ++nb) {
                const int m = m_base + mt * 16 + g;
                const int n = n_base + nb * 8 + 2 * q;
                float* p0 = s_stage + m * STAGE_STRIDE + n;
                p0[0] = acc[mt * 4 + nb][0];
                p0[1] = acc[mt * 4 + nb][1];
                float* p1 = p0 + 8 * STAGE_STRIDE;
                p1[0] = acc[mt * 4 + nb][2];
                p1[1] = acc[mt * 4 + nb][3];
            }
    }
    __syncthreads();

    /* ---- epilogue: gates + state; h written as fp16 ---- */
    if (tid < 256) {
        const float* sp = s_stage + tid * STAGE_STRIDE;
        const int pix = ((y0 + (tid >> 7)) << 8) + x0 + (tid & 127);
        #pragma unroll
        for (int hid = 0; hid < HID; ++hid) {
            const float iv = sp[hid]      + bc[hid];
            const float fv = sp[hid + 16] + bc[hid + 16];
            const float ov = sp[hid + 32] + bc[hid + 32];
            const float gv = sp[hid + 48] + bc[hid + 48];
            const int idx = ((b * HID + hid) << 16) + pix;
            const float cold = first ? 0.0f : g_c[idx];
            const float i = sig_(iv), f = sig_(fv), o = sig_(ov), g = tanh_(gv);
            const float c = f * cold + i * g;
            g_c[idx]     = c;
            hh_next[idx] = __float2half_rn(o * tanh_(c));
        }
    }
}

/* Final 1x1 conv over fp16 h_last (g_hh[0] after 12 steps). 8 px per thread. */
__global__ void final_conv_kernel(const float* __restrict__ Wf,
                                  const float* __restrict__ bfin,
                                  float* __restrict__ out)
{
    const int total8 = BATCH * IMG * IMG / 8;
    int idx8 = blockIdx.x * blockDim.x + threadIdx.x;
    if (idx8 >= total8) return;
    const __half* h = g_hh[TSTEPS & 1];
    int b    = idx8 >> 13;
    int pix8 = idx8 & 8191;
    float w[HID];
    #pragma unroll
    for (int jj = 0; jj < HID; ++jj) w[jj] = Wf[jj];
    float bv = bfin[0];
    float a[8];
    #pragma unroll
    for (int p = 0; p < 8; ++p) a[p] = bv;
    #pragma unroll
    for (int jj = 0; jj < HID; ++jj) {
        const __half* hp = h + ((b * HID + jj) << 16) + pix8 * 8;
        uint4 v = *(const uint4*)hp;
        const __half2* h2 = (const __half2*)&v;
        #pragma unroll
        for (int q = 0; q < 4; ++q) {
            float2 f2 = __half22float2(h2[q]);
            a[2 * q]     += w[jj] * f2.x;
            a[2 * q + 1] += w[jj] * f2.y;
        }
    }
    float4* o = (float4*)(out + ((b << 16) + pix8 * 8));
    o[0] = make_float4(a[0], a[1], a[2], a[3]);
    o[1] = make_float4(a[4], a[5], a[6], a[7]);
}

extern "C" void kernel_launch(void* const* d_in, const int* in_sizes, int n_in,
                              void* d_out, int out_size)
{
    const float* x  = (const float*)d_in[0];
    const float* Wc = (const float*)d_in[1];
    const float* bc = (const float*)d_in[2];
    const float* Wf = (const float*)d_in[3];
    const float* bf = (const float*)d_in[4];
    float* out = (float*)d_out;

    cudaFuncSetAttribute(lstm_step_kernel,
                         cudaFuncAttributeMaxDynamicSharedMemorySize, SMEM_TOTAL);

    build_B_kernel<<<1, 192>>>(Wc);

    dim3 grid(IMG / 128, IMG / 2, BATCH);   /* 2048 CTAs */
    for (int t = 0; t < TSTEPS; ++t)
        lstm_step_kernel<<<grid, NTHREADS, SMEM_TOTAL>>>(x, bc, t);

    const int total8 = BATCH * IMG * IMG / 8;
    final_conv_kernel<<<(total8 + 255) / 256, 256>>>(Wf, bf, out);
}

// round 15
// speedup vs baseline: 5.1059x; 1.2076x over previous
#include <cuda_runtime.h>
#include <cuda_fp16.h>
#include <cstdint>

#define BATCH   8
#define TSTEPS  12
#define CIN_X   5
#define HID     16
#define IMG     256
#define NTHREADS 512

/* smem: A (fp16) [512 rows][64 f16] = 65536 B; B (fp16) 3 dy x 8192 B */
#define SM_A       0
#define SM_B(dy)   (65536 + (dy) * 8192)
#define SMEM_TOTAL 90112               /* 88 KB -> 2 CTAs/SM */
#define STAGE_STRIDE 68                /* f32 stage: 256*68*4 = 69632 <= total */

/* h state: [2][b][pix][ch] fp16 (channel-contiguous per pixel) */
__device__ __half g_hh[2][BATCH * IMG * IMG * HID];
/* c state: [b][pix][ch] fp32 */
__device__ float  g_c [BATCH * IMG * IMG * HID];
__device__ uint4  g_B [3 * 512];

__device__ __forceinline__ uint32_t smem_u32(const void* p) {
    uint32_t a;
    asm("{ .reg .u64 t; cvta.to.shared.u64 t, %1; cvt.u32.u64 %0, t; }" : "=r"(a) : "l"(p));
    return a;
}
__device__ __forceinline__ void ldsm4(uint32_t* r, uint32_t addr) {
    asm volatile("ldmatrix.sync.aligned.m8n8.x4.shared.b16 {%0,%1,%2,%3}, [%4];"
                 : "=r"(r[0]), "=r"(r[1]), "=r"(r[2]), "=r"(r[3]) : "r"(addr));
}
__device__ __forceinline__ void mma16816(float* c, const uint32_t* a, uint32_t b0, uint32_t b1) {
    asm volatile("mma.sync.aligned.m16n8k16.row.col.f32.f16.f16.f32 "
                 "{%0,%1,%2,%3}, {%4,%5,%6,%7}, {%8,%9}, {%0,%1,%2,%3};"
                 : "+f"(c[0]), "+f"(c[1]), "+f"(c[2]), "+f"(c[3])
                 : "r"(a[0]), "r"(a[1]), "r"(a[2]), "r"(a[3]), "r"(b0), "r"(b1));
}
__device__ __forceinline__ float sig_(float x)  { return 1.0f / (1.0f + __expf(-x)); }
__device__ __forceinline__ float tanh_(float x) { return 2.0f / (1.0f + __expf(-2.0f * x)) - 1.0f; }

/* K ordering: k in [0,48): h tap, dx = k>>4, ch = k&15 (in-ch = 5+ch)
               k in [48,63): x tap, dx = (k-48)/5, ch = (k-48)%5
               k = 63: pad */
__device__ __forceinline__ float wk(const float* Wc, int n, int dy, int k) {
    if (k < 48) { int dx = k >> 4;  int ch = k & 15;       return Wc[n * 189 + (5 + ch) * 9 + dy * 3 + dx]; }
    if (k < 63) { int q = k - 48;   int dx = q / 5;
                  int ch = q - 5 * dx;                     return Wc[n * 189 + ch * 9 + dy * 3 + dx]; }
    return 0.0f;
}

/* Precompute B (fp16) swizzled smem image. 192 threads: (dy, n). */
__global__ void build_B_kernel(const float* __restrict__ Wc)
{
    const int tid = threadIdx.x;
    if (tid >= 192) return;
    const int dy = tid >> 6;
    const int n  = tid & 63;
    #pragma unroll
    for (int i = 0; i < 8; ++i) {
        uint32_t hp[4];
        #pragma unroll
        for (int jj = 0; jj < 4; ++jj) {
            float v0 = wk(Wc, n, dy, i * 8 + 2 * jj);
            float v1 = wk(Wc, n, dy, i * 8 + 2 * jj + 1);
            hp[jj] = (uint32_t)__half_as_ushort(__float2half_rn(v0)) |
                     ((uint32_t)__half_as_ushort(__float2half_rn(v1)) << 16);
        }
        uint32_t off = (uint32_t)(n * 128 + i * 16);
        off ^= (uint32_t)((n & 7) << 4);
        g_B[(dy * 8192 + (int)off) >> 4] = make_uint4(hp[0], hp[1], hp[2], hp[3]);
    }
}

/* Fused ConvLSTM step: single-pass fp16 mma.sync implicit GEMM.
   CTA: (b, y0=2*by, x0) -> 2 output rows x 128 px (M=256). 16 warps (8m x 2n).
   h state is [pix][ch] so A rows are built by direct 16B copies. */
__global__ void __launch_bounds__(NTHREADS, 2)
lstm_step_kernel(const float* __restrict__ xall, const float* __restrict__ bc, int t)
{
    extern __shared__ char smem[];
    const uint32_t sb = smem_u32(smem);
    float* s_stage = (float*)smem;

    const int tid  = threadIdx.x;
    const int wid  = tid >> 5;
    const int lane = tid & 31;
    const int b  = blockIdx.z;
    const int y0 = blockIdx.y << 1;
    const int x0 = blockIdx.x << 7;
    const int first = (t == 0);

    const __half* hh_prev = g_hh[t & 1];
    __half*       hh_next = g_hh[(t + 1) & 1];

    /* ---- copy B image (24 KB) ---- */
    {
        uint4* dst = (uint4*)(smem + SM_B(0));
        #pragma unroll 1
        for (int i = tid; i < 1536; i += NTHREADS) dst[i] = g_B[i];
    }
    /* ---- build A: one (strip, px) per thread; A row index = tid ---- */
    {
        const int r  = tid >> 7;            /* input strip 0..3 */
        const int m  = tid & 127;
        const int gy = y0 - 1 + r;
        const bool rowok = ((unsigned)gy < IMG);
        uint4 q[8];
        /* h taps: 3 neighbor pixels x 16 ch, direct 2x16B copies each */
        #pragma unroll
        for (int dx = 0; dx < 3; ++dx) {
            const int gx = x0 + m - 1 + dx;
            uint4 lo = make_uint4(0, 0, 0, 0), hi = make_uint4(0, 0, 0, 0);
            if (rowok && (unsigned)gx < IMG && !first) {
                const uint4* hp = (const uint4*)(hh_prev +
                    ((size_t)((b << 16) + (gy << 8) + gx)) * HID);
                lo = hp[0]; hi = hp[1];
            }
            q[dx * 2]     = lo;
            q[dx * 2 + 1] = hi;
        }
        /* x taps: 15 fp32 loads + cvt into k 48..62 (pad k=63) */
        {
            unsigned short xs[16];
            #pragma unroll
            for (int e = 0; e < 16; ++e) xs[e] = 0;
            #pragma unroll
            for (int dx = 0; dx < 3; ++dx) {
                const int gx = x0 + m - 1 + dx;
                const bool ok = rowok && ((unsigned)gx < IMG);
                #pragma unroll
                for (int ch = 0; ch < 5; ++ch) {
                    if (ok)
                        xs[dx * 5 + ch] = __half_as_ushort(__float2half_rn(
                            xall[(((b * TSTEPS + t) * CIN_X + ch) << 16) + (gy << 8) + gx]));
                }
            }
            uint32_t* xw = (uint32_t*)&q[6];
            #pragma unroll
            for (int e = 0; e < 8; ++e)
                xw[e] = (uint32_t)xs[2 * e] | ((uint32_t)xs[2 * e + 1] << 16);
        }
        #pragma unroll
        for (int qi = 0; qi < 8; ++qi) {
            uint32_t off = (uint32_t)(tid * 128 + qi * 16);
            off ^= (uint32_t)((tid & 7) << 4);
            *(uint4*)(smem + SM_A + off) = q[qi];
        }
    }
    __syncthreads();

    /* ---- mainloop: 12 iters x (4 ldsm + 8 mma) ---- */
    const int wm = wid >> 1;
    const int wn = wid & 1;
    const int m_base = wm * 32;
    const int n_base = wn * 32;
    const int j  = lane >> 3;
    const int rr = lane & 7;

    uint32_t offA[2], offB[2];
    #pragma unroll
    for (int mt = 0; mt < 2; ++mt) {
        const int row = m_base + mt * 16 + (j & 1) * 8 + rr;
        const int c16 = j >> 1;
        offA[mt] = (uint32_t)(row * 128 + ((c16 << 4) ^ ((row & 7) << 4)));
    }
    #pragma unroll
    for (int nb = 0; nb < 2; ++nb) {
        const int row = n_base + nb * 16 + (j >> 1) * 8 + rr;
        const int c16 = j & 1;
        offB[nb] = (uint32_t)(row * 128 + ((c16 << 4) ^ ((row & 7) << 4)));
    }

    float acc[8][4];
    #pragma unroll
    for (int q = 0; q < 8; ++q)
        #pragma unroll
        for (int e = 0; e < 4; ++e) acc[q][e] = 0.0f;

    #pragma unroll
    for (int it = 0; it < 12; ++it) {
        const int dy = it >> 2;
        const uint32_t kx = (uint32_t)((it & 3) << 5);
        const uint32_t Ab = sb + SM_A + (uint32_t)(dy * 16384);
        uint32_t a0[4], a1[4], b0[4], b1[4];
        ldsm4(a0, Ab + (offA[0] ^ kx));
        ldsm4(a1, Ab + (offA[1] ^ kx));
        ldsm4(b0, sb + SM_B(dy) + (offB[0] ^ kx));
        ldsm4(b1, sb + SM_B(dy) + (offB[1] ^ kx));
        mma16816(acc[0], a0, b0[0], b0[1]);
        mma16816(acc[1], a0, b0[2], b0[3]);
        mma16816(acc[2], a0, b1[0], b1[1]);
        mma16816(acc[3], a0, b1[2], b1[3]);
        mma16816(acc[4], a1, b0[0], b0[1]);
        mma16816(acc[5], a1, b0[2], b0[3]);
        mma16816(acc[6], a1, b1[0], b1[1]);
        mma16816(acc[7], a1, b1[2], b1[3]);
    }
    __syncthreads();

    /* ---- stage acc -> smem f32 [256][68] ---- */
    {
        const int g = lane >> 2;
        const int q = lane & 3;
        #pragma unroll
        for (int mt = 0; mt < 2; ++mt)
            #pragma unroll
            for (int nb = 0; nb < 4; ++nb) {
                const int m = m_base + mt * 16 + g;
                const int n = n_base + nb * 8 + 2 * q;
                float* p0 = s_stage + m * STAGE_STRIDE + n;
                p0[0] = acc[mt * 4 + nb][0];
                p0[1] = acc[mt * 4 + nb][1];
                float* p1 = p0 + 8 * STAGE_STRIDE;
                p1[0] = acc[mt * 4 + nb][2];
                p1[1] = acc[mt * 4 + nb][3];
            }
    }
    __syncthreads();

    /* ---- epilogue: all 512 threads; 2 threads/pixel x 8 ch ---- */
    {
        const int pl   = tid >> 1;          /* pixel local 0..255 */
        const int half = tid & 1;           /* ch 8*half..8*half+7 */
        const float* sp = s_stage + pl * STAGE_STRIDE + half * 8;
        const int pix = ((y0 + (pl >> 7)) << 8) + x0 + (pl & 127);
        const int base = ((b << 16) + pix) * HID + half * 8;

        float4 iva = *(const float4*)(sp);      float4 ivb = *(const float4*)(sp + 4);
        float4 fva = *(const float4*)(sp + 16); float4 fvb = *(const float4*)(sp + 20);
        float4 ova = *(const float4*)(sp + 32); float4 ovb = *(const float4*)(sp + 36);
        float4 gva = *(const float4*)(sp + 48); float4 gvb = *(const float4*)(sp + 52);
        float iv[8] = {iva.x, iva.y, iva.z, iva.w, ivb.x, ivb.y, ivb.z, ivb.w};
        float fv[8] = {fva.x, fva.y, fva.z, fva.w, fvb.x, fvb.y, fvb.z, fvb.w};
        float ov[8] = {ova.x, ova.y, ova.z, ova.w, ovb.x, ovb.y, ovb.z, ovb.w};
        float gv[8] = {gva.x, gva.y, gva.z, gva.w, gvb.x, gvb.y, gvb.z, gvb.w};

        float cold[8];
        if (!first) {
            float4 c0 = *(const float4*)(g_c + base);
            float4 c1 = *(const float4*)(g_c + base + 4);
            cold[0] = c0.x; cold[1] = c0.y; cold[2] = c0.z; cold[3] = c0.w;
            cold[4] = c1.x; cold[5] = c1.y; cold[6] = c1.z; cold[7] = c1.w;
        } else {
            #pragma unroll
            for (int e = 0; e < 8; ++e) cold[e] = 0.0f;
        }

        float cn[8];
        unsigned short hn[8];
        #pragma unroll
        for (int e = 0; e < 8; ++e) {
            const int hid = half * 8 + e;
            const float i = sig_(iv[e] + bc[hid]);
            const float f = sig_(fv[e] + bc[hid + 16]);
            const float o = sig_(ov[e] + bc[hid + 32]);
            const float g = tanh_(gv[e] + bc[hid + 48]);
            const float c = f * cold[e] + i * g;
            cn[e] = c;
            hn[e] = __half_as_ushort(__float2half_rn(o * tanh_(c)));
        }
        *(float4*)(g_c + base)     = make_float4(cn[0], cn[1], cn[2], cn[3]);
        *(float4*)(g_c + base + 4) = make_float4(cn[4], cn[5], cn[6], cn[7]);
        uint4 hv;
        hv.x = (uint32_t)hn[0] | ((uint32_t)hn[1] << 16);
        hv.y = (uint32_t)hn[2] | ((uint32_t)hn[3] << 16);
        hv.z = (uint32_t)hn[4] | ((uint32_t)hn[5] << 16);
        hv.w = (uint32_t)hn[6] | ((uint32_t)hn[7] << 16);
        *(uint4*)(hh_next + base) = hv;
    }
}

/* Final 1x1 conv over [pix][ch] fp16 h_last. 4 px per thread. */
__global__ void final_conv_kernel(const float* __restrict__ Wf,
                                  const float* __restrict__ bfin,
                                  float* __restrict__ out)
{
    const int total4 = BATCH * IMG * IMG / 4;
    int p4 = blockIdx.x * blockDim.x + threadIdx.x;
    if (p4 >= total4) return;
    const __half* h = g_hh[TSTEPS & 1];
    const int b    = p4 >> 14;
    const int pix0 = (p4 & 16383) * 4;
    float w[HID];
    #pragma unroll
    for (int jj = 0; jj < HID; ++jj) w[jj] = Wf[jj];
    const float bv = bfin[0];
    float a[4];
    #pragma unroll
    for (int p = 0; p < 4; ++p) {
        const __half2* hp = (const __half2*)(h + ((size_t)((b << 16) + pix0 + p)) * HID);
        float s = bv;
        #pragma unroll
        for (int q = 0; q < 8; ++q) {
            float2 f2 = __half22float2(hp[q]);
            s += w[2 * q] * f2.x + w[2 * q + 1] * f2.y;
        }
        a[p] = s;
    }
    ((float4*)out)[p4] = make_float4(a[0], a[1], a[2], a[3]);
}

extern "C" void kernel_launch(void* const* d_in, const int* in_sizes, int n_in,
                              void* d_out, int out_size)
{
    const float* x  = (const float*)d_in[0];
    const float* Wc = (const float*)d_in[1];
    const float* bc = (const float*)d_in[2];
    const float* Wf = (const float*)d_in[3];
    const float* bf = (const float*)d_in[4];
    float* out = (float*)d_out;

    cudaFuncSetAttribute(lstm_step_kernel,
                         cudaFuncAttributeMaxDynamicSharedMemorySize, SMEM_TOTAL);

    build_B_kernel<<<1, 192>>>(Wc);

    dim3 grid(IMG / 128, IMG / 2, BATCH);   /* 2048 CTAs */
    for (int t = 0; t < TSTEPS; ++t)
        lstm_step_kernel<<<grid, NTHREADS, SMEM_TOTAL>>>(x, bc, t);

    const int total4 = BATCH * IMG * IMG / 4;
    final_conv_kernel<<<(total4 + 511) / 512, 512>>>(Wf, bf, out);
}